// round 10
// baseline (speedup 1.0000x reference)
#include <cuda_runtime.h>
#include <cuda_bf16.h>
#include <stdint.h>
#include <cstdint>
#include <math.h>

// ---------------- problem constants ----------------
#define Bn   64
#define Kn   64
#define Np   32768
#define Dn   2048
#define NCn  2048
#define NH   512
#define CDn  4096      // 2*Dn
#define RWS  4096      // Bn*Kn

// ---------------- device scratch ----------------
__device__ int   g_offsets[NCn + 1];
__device__ int   g_bucket[Np];
__device__ int   g_used[NCn];
__device__ float g_clu[(size_t)NCn * Dn];          // 16 MB cluster means
__device__ float g_x[(size_t)RWS * Dn];            // 32 MB fp32 raw cf
__device__ __nv_bfloat16 g_catb[(size_t)RWS * CDn];// 32 MB bf16 [x | agg]
__device__ __nv_bfloat16 g_adjb[RWS * Kn];         // 0.5 MB bf16 masked adj
__device__ float g_apart[8 * Bn * Kn * Kn];        // 8 MB split-K partials
__device__ float g_rinv[RWS];
__device__ __nv_bfloat16 g_hb[(size_t)RWS * NH];   // 4 MB
__device__ __nv_bfloat16 g_h1b[(size_t)RWS * NH];  // 4 MB
__device__ __nv_bfloat16 g_wb[(size_t)CDn * NH];   // 4 MB
__device__ __nv_bfloat16 g_w1b[NH * NH];           // 0.5 MB

// ---------------- bucketing: count+scan+scatter + used-cluster mark ----------------
__global__ void __launch_bounds__(1024) bucket_k(const int* __restrict__ labels,
                                                 const int* __restrict__ nbr) {
    __shared__ int s[NCn];
    __shared__ int cur[NCn];
    int t = threadIdx.x;
    s[t] = 0; s[t + 1024] = 0;
    g_used[t] = 0; g_used[t + 1024] = 0;
    __syncthreads();
    for (int n = t; n < Np; n += 1024) atomicAdd(&s[labels[n]], 1);
    // mark clusters actually referenced by any sample's neighbor list
    for (int n = t; n < Bn * Kn; n += 1024) g_used[labels[nbr[n]]] = 1;
    __syncthreads();
    for (int off = 1; off < NCn; off <<= 1) {
        int v0 = (t >= off) ? s[t - off] : 0;
        int v1 = s[t + 1024 - off];
        __syncthreads();
        s[t]        += v0;
        s[t + 1024] += v1;
        __syncthreads();
    }
    int off0 = (t == 0) ? 0 : s[t - 1];
    int off1 = s[t + 1023];
    g_offsets[t]        = off0;
    g_offsets[t + 1024] = off1;
    if (t == 0) g_offsets[NCn] = s[NCn - 1];
    cur[t] = off0; cur[t + 1024] = off1;
    __syncthreads();
    for (int n = t; n < Np; n += 1024) {
        int pos = atomicAdd(&cur[labels[n]], 1);
        g_bucket[pos] = n;
    }
}

// grid-parallel per-bucket sort -> deterministic summation order
__global__ void sortbucket_k() {
    int c = blockIdx.x * blockDim.x + threadIdx.x;
    if (c >= NCn) return;
    if (!g_used[c]) return;
    int s = g_offsets[c], e = g_offsets[c + 1];
    for (int i = s + 1; i < e; i++) {
        int v = g_bucket[i];
        int j = i - 1;
        while (j >= s && g_bucket[j] > v) { g_bucket[j + 1] = g_bucket[j]; j--; }
        g_bucket[j + 1] = v;
    }
}

// ---------------- weight conversion to bf16 ----------------
__global__ void convw_k(const float* __restrict__ w, const float* __restrict__ w1) {
    int i = blockIdx.x * 256 + threadIdx.x;
    if (i < CDn * NH) g_wb[i] = __float2bfloat16(w[i]);
    if (i < NH * NH)  g_w1b[i] = __float2bfloat16(w1[i]);
}

// float4, 4 accumulator streams; only used clusters; grid (Dn/1024, NCn), 256 thr
__global__ void clumean_k(const float* __restrict__ features) {
    int c = blockIdx.y;
    if (!g_used[c]) return;
    int d4 = blockIdx.x * 256 + threadIdx.x;       // float4 column index
    int s = g_offsets[c], e = g_offsets[c + 1];
    float4 s0 = make_float4(0.f, 0.f, 0.f, 0.f);
    float4 s1 = s0, s2 = s0, s3 = s0;
    int m = s;
    for (; m + 3 < e; m += 4) {
        int i0 = g_bucket[m], i1 = g_bucket[m + 1];
        int i2 = g_bucket[m + 2], i3 = g_bucket[m + 3];
        float4 a = ((const float4*)(features + (size_t)i0 * Dn))[d4];
        float4 b = ((const float4*)(features + (size_t)i1 * Dn))[d4];
        float4 cc = ((const float4*)(features + (size_t)i2 * Dn))[d4];
        float4 dd = ((const float4*)(features + (size_t)i3 * Dn))[d4];
        s0.x += a.x;  s0.y += a.y;  s0.z += a.z;  s0.w += a.w;
        s1.x += b.x;  s1.y += b.y;  s1.z += b.z;  s1.w += b.w;
        s2.x += cc.x; s2.y += cc.y; s2.z += cc.z; s2.w += cc.w;
        s3.x += dd.x; s3.y += dd.y; s3.z += dd.z; s3.w += dd.w;
    }
    for (; m < e; m++) {
        float4 a = ((const float4*)(features + (size_t)g_bucket[m] * Dn))[d4];
        s0.x += a.x; s0.y += a.y; s0.z += a.z; s0.w += a.w;
    }
    float4 sum;
    sum.x = (s0.x + s1.x) + (s2.x + s3.x);
    sum.y = (s0.y + s1.y) + (s2.y + s3.y);
    sum.z = (s0.z + s1.z) + (s2.z + s3.z);
    sum.w = (s0.w + s1.w) + (s2.w + s3.w);
    float inv = 1.f / fmaxf((float)(e - s), 1.f);
    sum.x *= inv; sum.y *= inv; sum.z *= inv; sum.w *= inv;
    ((float4*)(g_clu + (size_t)c * Dn))[d4] = sum;
}

// ---------------- cf build + fused row-norm ----------------
__global__ void build_cf_norm_k(const int* __restrict__ indexes,
                                const float* __restrict__ features,
                                const int* __restrict__ labels,
                                const int* __restrict__ nbr) {
    int r = blockIdx.x, t = threadIdx.x;
    int b = r >> 6, k = r & 63;
    const float* src;
    if (k == 0) src = features + (size_t)indexes[b] * Dn;
    else        src = g_clu + (size_t)labels[nbr[r]] * Dn;
    const float4* s4 = (const float4*)src;
    float4* d4 = (float4*)(g_x + (size_t)r * Dn);
    float s = 0.f;
    #pragma unroll
    for (int i = t; i < Dn / 4; i += 256) {
        float4 v = s4[i];
        d4[i] = v;
        s += v.x * v.x + v.y * v.y + v.z * v.z + v.w * v.w;
    }
    __shared__ float red[8];
    #pragma unroll
    for (int o = 16; o; o >>= 1) s += __shfl_xor_sync(0xffffffffu, s, o);
    if ((t & 31) == 0) red[t >> 5] = s;
    __syncthreads();
    if (t < 8) {
        float v = red[t];
        #pragma unroll
        for (int o = 4; o; o >>= 1) v += __shfl_xor_sync(0xffu, v, o);
        if (t == 0) g_rinv[r] = 1.f / sqrtf(v);
    }
}

// ---------------- tensor-core helpers ----------------
__device__ __forceinline__ void ldsm4(unsigned* r, unsigned a) {
    asm volatile("ldmatrix.sync.aligned.m8n8.x4.shared.b16 {%0,%1,%2,%3}, [%4];"
        : "=r"(r[0]), "=r"(r[1]), "=r"(r[2]), "=r"(r[3]) : "r"(a));
}
__device__ __forceinline__ void ldsm4t(unsigned* r, unsigned a) {
    asm volatile("ldmatrix.sync.aligned.m8n8.x4.trans.shared.b16 {%0,%1,%2,%3}, [%4];"
        : "=r"(r[0]), "=r"(r[1]), "=r"(r[2]), "=r"(r[3]) : "r"(a));
}
__device__ __forceinline__ void mma16816(float* c, const unsigned* a, unsigned b0, unsigned b1) {
    asm volatile("mma.sync.aligned.m16n8k16.row.col.f32.bf16.bf16.f32 "
        "{%0,%1,%2,%3}, {%4,%5,%6,%7}, {%8,%9}, {%0,%1,%2,%3};"
        : "+f"(c[0]), "+f"(c[1]), "+f"(c[2]), "+f"(c[3])
        : "r"(a[0]), "r"(a[1]), "r"(a[2]), "r"(a[3]), "r"(b0), "r"(b1));
}
__device__ __forceinline__ void cpasync16(unsigned dst, const void* src) {
    asm volatile("cp.async.cg.shared.global [%0], [%1], 16;"
        :: "r"(dst), "l"(__cvta_generic_to_global(src)));
}
__device__ __forceinline__ void cpcommit() {
    asm volatile("cp.async.commit_group;");
}

// ---------------- A partials = cf cf^T over K-chunk 256 (split-bf16 TC) ----------------
// grid (8, Bn), 256 threads; C = Xhi Xhi^T + Xhi Xlo^T + Xlo Xhi^T (fp32 acc)
__global__ void __launch_bounds__(256) absplit_k() {
    __shared__ __nv_bfloat16 Shi[2][64 * 64];
    __shared__ __nv_bfloat16 Slo[2][64 * 64];
    int chunk = blockIdx.x, b = blockIdx.y, tid = threadIdx.x;
    int lane = tid & 31, warp = tid >> 5;
    int wm = (warp & 3) * 16, wn = (warp >> 2) * 32;
    unsigned hi_u = (unsigned)__cvta_generic_to_shared(Shi);
    unsigned lo_u = (unsigned)__cvta_generic_to_shared(Slo);

    int lr = tid >> 2;             // 0..63 loader row
    int lc = (tid & 3) * 16;       // loader col base
    const float* src = g_x + (size_t)(b * 64 + lr) * Dn + chunk * 256 + lc;

    float f[16];
    float acc[4][4] = {};

    {
        const float4* p = (const float4*)src;
        #pragma unroll
        for (int i = 0; i < 4; i++) *(float4*)&f[i * 4] = p[i];
    }

    #pragma unroll
    for (int t = 0; t < 4; t++) {
        int s = t & 1;
        {
            __nv_bfloat16 h[16], l[16];
            #pragma unroll
            for (int i = 0; i < 16; i++) {
                h[i] = __float2bfloat16(f[i]);
                l[i] = __float2bfloat16(f[i] - __bfloat162float(h[i]));
            }
            int c0 = lc >> 3;
            #pragma unroll
            for (int half = 0; half < 2; half++) {
                int c = c0 + half;
                int off = lr * 64 + ((c ^ (lr & 7)) * 8);
                uint4 uh, ul;
                __nv_bfloat162 t2;
                t2 = __nv_bfloat162(h[half * 8 + 0], h[half * 8 + 1]); uh.x = *(unsigned*)&t2;
                t2 = __nv_bfloat162(h[half * 8 + 2], h[half * 8 + 3]); uh.y = *(unsigned*)&t2;
                t2 = __nv_bfloat162(h[half * 8 + 4], h[half * 8 + 5]); uh.z = *(unsigned*)&t2;
                t2 = __nv_bfloat162(h[half * 8 + 6], h[half * 8 + 7]); uh.w = *(unsigned*)&t2;
                t2 = __nv_bfloat162(l[half * 8 + 0], l[half * 8 + 1]); ul.x = *(unsigned*)&t2;
                t2 = __nv_bfloat162(l[half * 8 + 2], l[half * 8 + 3]); ul.y = *(unsigned*)&t2;
                t2 = __nv_bfloat162(l[half * 8 + 4], l[half * 8 + 5]); ul.z = *(unsigned*)&t2;
                t2 = __nv_bfloat162(l[half * 8 + 6], l[half * 8 + 7]); ul.w = *(unsigned*)&t2;
                *(uint4*)&Shi[s][off] = uh;
                *(uint4*)&Slo[s][off] = ul;
            }
        }
        __syncthreads();
        if (t + 1 < 4) {
            const float4* p = (const float4*)(src + (t + 1) * 64);
            #pragma unroll
            for (int i = 0; i < 4; i++) *(float4*)&f[i * 4] = p[i];
        }
        unsigned base_h = hi_u + (unsigned)(s * 8192);
        unsigned base_l = lo_u + (unsigned)(s * 8192);
        #pragma unroll
        for (int k16 = 0; k16 < 4; k16++) {
            unsigned ahi[4], alo[4], bh[2][4], bl[2][4];
            int ac = k16 * 2 + (lane >> 4);
            int arow = wm + (lane & 15);
            unsigned aoff = (unsigned)((arow * 64 + ((ac ^ (arow & 7)) * 8)) * 2);
            ldsm4(ahi, base_h + aoff);
            ldsm4(alo, base_l + aoff);
            #pragma unroll
            for (int nt = 0; nt < 2; nt++) {
                int brow = wn + nt * 16 + (lane & 15);
                unsigned boff = (unsigned)((brow * 64 + ((ac ^ (brow & 7)) * 8)) * 2);
                ldsm4(bh[nt], base_h + boff);
                ldsm4(bl[nt], base_l + boff);
            }
            #pragma unroll
            for (int nt = 0; nt < 2; nt++) {
                mma16816(acc[nt * 2 + 0], ahi, bh[nt][0], bh[nt][2]);
                mma16816(acc[nt * 2 + 0], ahi, bl[nt][0], bl[nt][2]);
                mma16816(acc[nt * 2 + 0], alo, bh[nt][0], bh[nt][2]);
                mma16816(acc[nt * 2 + 1], ahi, bh[nt][1], bh[nt][3]);
                mma16816(acc[nt * 2 + 1], ahi, bl[nt][1], bl[nt][3]);
                mma16816(acc[nt * 2 + 1], alo, bh[nt][1], bh[nt][3]);
            }
        }
        __syncthreads();
    }

    // write partials (unscaled)
    float* dst = g_apart + (size_t)(chunk * Bn + b) * 4096;
    int gid = lane >> 2, tid4 = lane & 3;
    #pragma unroll
    for (int t = 0; t < 4; t++) {
        int n = wn + t * 8 + tid4 * 2;
        int m = wm + gid;
        dst[m * 64 + n]           = acc[t][0];
        dst[m * 64 + n + 1]       = acc[t][1];
        dst[(m + 8) * 64 + n]     = acc[t][2];
        dst[(m + 8) * 64 + n + 1] = acc[t][3];
    }
}

// fused: deterministic reduce of 8 partials (+/5) -> keep + mutual top-5 -> bf16 adj
__global__ void __launch_bounds__(256) maskred_k(const int* __restrict__ labels,
                                                 const int* __restrict__ nbr) {
    __shared__ float As[64][65];
    __shared__ unsigned long long rm[64];
    __shared__ int lab[64];
    __shared__ int keep[64];
    int b = blockIdx.x, t = threadIdx.x;   // 256 threads
    for (int loc = t; loc < 4096; loc += 256) {
        float s = 0.f;
        #pragma unroll
        for (int c = 0; c < 8; c++) s += g_apart[(size_t)(c * Bn + b) * 4096 + loc];
        As[loc >> 6][loc & 63] = s * 0.2f;
    }
    if (t < 64) lab[t] = labels[nbr[b * 64 + t]];
    __syncthreads();
    if (t < 64) {
        int dup = 0;
        for (int j = 0; j < t; j++) dup |= (lab[j] == lab[t]);
        keep[t] = !dup;
        unsigned long long sel = 0ULL;
        for (int r = 0; r < 5; r++) {
            float best = -3.4e38f; int bi = 0;
            for (int j = 0; j < 64; j++) {
                float v = As[t][j];
                if (!((sel >> j) & 1ULL) && v > best) { best = v; bi = j; }
            }
            sel |= 1ULL << bi;
        }
        rm[t] = sel;
    }
    __syncthreads();
    if (t < 64) {
        bool kt = keep[t];
        for (int j = 0; j < 64; j++) {
            bool mm = kt && keep[j] && ((rm[t] >> j) & 1ULL) && ((rm[j] >> t) & 1ULL);
            g_adjb[(b * 64 + t) * 64 + j] = __float2bfloat16(mm ? As[t][j] : 0.f);
        }
    }
}

// x = cf/||cf|| - q, vectorized; row 0 cancels exactly
__global__ void center_k() {
    int r = blockIdx.x, t = threadIdx.x;
    int b = r >> 6;
    float rv = g_rinv[r];
    float qv = g_rinv[b * 64];
    const float4* xr4 = (const float4*)(g_x + (size_t)r * Dn);
    const float4* xq4 = (const float4*)(g_x + (size_t)(b * 64) * Dn);
    #pragma unroll
    for (int i = t; i < Dn / 4; i += 256) {
        float4 a = xr4[i], q = xq4[i];
        __nv_bfloat162 p0 = __floats2bfloat162_rn(a.x * rv - q.x * qv, a.y * rv - q.y * qv);
        __nv_bfloat162 p1 = __floats2bfloat162_rn(a.z * rv - q.z * qv, a.w * rv - q.w * qv);
        uint2 u;
        u.x = *(unsigned*)&p0;
        u.y = *(unsigned*)&p1;
        *(uint2*)&g_catb[(size_t)r * CDn + i * 4] = u;
    }
}

// agg = adj @ x on tensor cores -> g_catb[:, Dn:2Dn]; grid (Dn/128, Bn), 128 thr
__global__ void __launch_bounds__(128) bagg_k() {
    __shared__ __nv_bfloat16 Aj[64 * 64];
    __shared__ __nv_bfloat16 Xs[64 * 128];
    int b = blockIdx.y, d0 = blockIdx.x * 128;
    int tid = threadIdx.x, lane = tid & 31, warp = tid >> 5;
    int wn = warp * 32;
    unsigned aj_u = (unsigned)__cvta_generic_to_shared(Aj);
    unsigned xs_u = (unsigned)__cvta_generic_to_shared(Xs);

    {
        int ar = tid >> 1, ac0 = (tid & 1) * 4;
        const __nv_bfloat16* src = g_adjb + (size_t)(b * 64 + ar) * 64 + ac0 * 8;
        #pragma unroll
        for (int i = 0; i < 4; i++) {
            uint4 v = *(const uint4*)(src + i * 8);
            int c = ac0 + i;
            *(uint4*)(Aj + ar * 64 + ((c ^ (ar & 7)) * 8)) = v;
        }
    }
    {
        int br = tid >> 2, bc0 = (tid & 3) * 4;
        #pragma unroll
        for (int h = 0; h < 64; h += 32) {
            int row = br + h;
            const __nv_bfloat16* src = g_catb + (size_t)(b * 64 + row) * CDn + d0 + bc0 * 8;
            #pragma unroll
            for (int i = 0; i < 4; i++) {
                uint4 v = *(const uint4*)(src + i * 8);
                int c = bc0 + i;
                int cs = (c & 8) | ((c & 7) ^ (row & 7));
                *(uint4*)(Xs + row * 128 + cs * 8) = v;
            }
        }
    }
    __syncthreads();

    float acc[4][4][4] = {};
    #pragma unroll
    for (int k16 = 0; k16 < 4; k16++) {
        unsigned afr[4][4], bfr[2][4];
        #pragma unroll
        for (int mi = 0; mi < 4; mi++) {
            int row = mi * 16 + (lane & 15);
            int c = k16 * 2 + (lane >> 4);
            ldsm4(afr[mi], aj_u + (row * 64 + ((c ^ (row & 7)) * 8)) * 2);
        }
        #pragma unroll
        for (int ni = 0; ni < 2; ni++) {
            int krow = k16 * 16 + (lane & 15);
            int c = (wn >> 3) + ni * 2 + (lane >> 4);
            int cs = (c & 8) | ((c & 7) ^ (krow & 7));
            ldsm4t(bfr[ni], xs_u + (krow * 128 + cs * 8) * 2);
        }
        #pragma unroll
        for (int mi = 0; mi < 4; mi++)
            #pragma unroll
            for (int ni = 0; ni < 2; ni++) {
                mma16816(acc[mi][ni * 2],     afr[mi], bfr[ni][0], bfr[ni][1]);
                mma16816(acc[mi][ni * 2 + 1], afr[mi], bfr[ni][2], bfr[ni][3]);
            }
    }
    int rr = lane >> 2, cc = (lane & 3) * 2;
    #pragma unroll
    for (int mi = 0; mi < 4; mi++) {
        int gm = mi * 16 + rr;
        #pragma unroll
        for (int ni = 0; ni < 4; ni++) {
            int gn = wn + ni * 8 + cc;
            size_t base0 = (size_t)(b * 64 + gm) * CDn + Dn + d0 + gn;
            size_t base1 = (size_t)(b * 64 + gm + 8) * CDn + Dn + d0 + gn;
            *(__nv_bfloat162*)&g_catb[base0] = __floats2bfloat162_rn(acc[mi][ni][0], acc[mi][ni][1]);
            *(__nv_bfloat162*)&g_catb[base1] = __floats2bfloat162_rn(acc[mi][ni][2], acc[mi][ni][3]);
        }
    }
}

// ---------------- 4-stage pipelined bf16 tensor-core GEMMs ----------------
// MODE 0: h  = relu(catb @ wb + conv_b)  -> g_hb  (bf16), K=4096
// MODE 1: h1 = prelu(hb @ w1b + b1, pa)  -> g_h1b (bf16), K=512
template <int MODE>
__global__ void __launch_bounds__(256) mgemm_k(const float* __restrict__ bias,
                                               const float* __restrict__ pa) {
    constexpr int Kd = (MODE == 0) ? CDn : NH;
    constexpr int nk = Kd / 64;
    const __nv_bfloat16* A = (MODE == 0) ? g_catb : g_hb;
    const __nv_bfloat16* W = (MODE == 0) ? g_wb : g_w1b;
    extern __shared__ __nv_bfloat16 smem[];
    int tid = threadIdx.x;
    int lane = tid & 31, warp = tid >> 5;
    int wm = (warp & 3) * 32, wn = (warp >> 2) * 64;
    int m0 = blockIdx.y * 128, n0 = blockIdx.x * 128;
    unsigned as_u = (unsigned)__cvta_generic_to_shared(smem);
    unsigned bs_u = as_u + 4 * 16384;

    int ar = tid >> 1, ac0 = (tid & 1) * 4;
    int br = tid >> 2, bc0 = (tid & 3) * 4;
    const __nv_bfloat16* Ag = A + (size_t)(m0 + ar) * Kd + ac0 * 8;
    const __nv_bfloat16* Wg = W + (size_t)br * NH + n0 + bc0 * 8;

    auto issue = [&](int it) {
        int s = it & 3;
        int k0 = it * 64;
        unsigned as_s = as_u + (unsigned)(s * 16384);
        unsigned bs_s = bs_u + (unsigned)(s * 16384);
        #pragma unroll
        for (int i = 0; i < 4; i++) {
            int c = ac0 + i;
            cpasync16(as_s + (unsigned)((ar * 64 + ((c ^ (ar & 7)) * 8)) * 2),
                      Ag + k0 + i * 8);
        }
        #pragma unroll
        for (int i = 0; i < 4; i++) {
            int c = bc0 + i;
            int cs = (c & 8) | ((c & 7) ^ (br & 7));
            cpasync16(bs_s + (unsigned)((br * 128 + cs * 8) * 2),
                      Wg + (size_t)k0 * NH + i * 8);
        }
        cpcommit();
    };

    float acc[2][8][4] = {};
    issue(0); issue(1); issue(2);
    for (int it = 0; it < nk; it++) {
        int s = it & 3;
        asm volatile("cp.async.wait_group 2;");
        __syncthreads();
        if (it + 3 < nk) issue(it + 3);
        unsigned as_s = as_u + (unsigned)(s * 16384);
        unsigned bs_s = bs_u + (unsigned)(s * 16384);
        #pragma unroll
        for (int k16 = 0; k16 < 4; k16++) {
            unsigned afr[2][4], bfr[4][4];
            #pragma unroll
            for (int mi = 0; mi < 2; mi++) {
                int row = wm + mi * 16 + (lane & 15);
                int c = k16 * 2 + (lane >> 4);
                ldsm4(afr[mi], as_s + (row * 64 + ((c ^ (row & 7)) * 8)) * 2);
            }
            #pragma unroll
            for (int ni = 0; ni < 4; ni++) {
                int krow = k16 * 16 + (lane & 15);
                int c = (wn >> 3) + ni * 2 + (lane >> 4);
                int cs = (c & 8) | ((c & 7) ^ (krow & 7));
                ldsm4t(bfr[ni], bs_s + (krow * 128 + cs * 8) * 2);
            }
            #pragma unroll
            for (int mi = 0; mi < 2; mi++)
                #pragma unroll
                for (int ni = 0; ni < 4; ni++) {
                    mma16816(acc[mi][ni * 2],     afr[mi], bfr[ni][0], bfr[ni][1]);
                    mma16816(acc[mi][ni * 2 + 1], afr[mi], bfr[ni][2], bfr[ni][3]);
                }
        }
    }

    int rr = lane >> 2, cc = (lane & 3) * 2;
    #pragma unroll
    for (int mi = 0; mi < 2; mi++) {
        int gm = m0 + wm + mi * 16 + rr;
        #pragma unroll
        for (int ni = 0; ni < 8; ni++) {
            int gn = n0 + wn + ni * 8 + cc;
            float b0 = bias[gn], b1 = bias[gn + 1];
            float v0 = acc[mi][ni][0] + b0;
            float v1 = acc[mi][ni][1] + b1;
            float v2 = acc[mi][ni][2] + b0;
            float v3 = acc[mi][ni][3] + b1;
            if (MODE == 0) {
                v0 = fmaxf(v0, 0.f); v1 = fmaxf(v1, 0.f);
                v2 = fmaxf(v2, 0.f); v3 = fmaxf(v3, 0.f);
                *(__nv_bfloat162*)&g_hb[(size_t)gm * NH + gn]       = __floats2bfloat162_rn(v0, v1);
                *(__nv_bfloat162*)&g_hb[(size_t)(gm + 8) * NH + gn] = __floats2bfloat162_rn(v2, v3);
            } else {
                float p0 = pa[gn], p1 = pa[gn + 1];
                v0 = (v0 > 0.f) ? v0 : p0 * v0;
                v1 = (v1 > 0.f) ? v1 : p1 * v1;
                v2 = (v2 > 0.f) ? v2 : p0 * v2;
                v3 = (v3 > 0.f) ? v3 : p1 * v3;
                *(__nv_bfloat162*)&g_h1b[(size_t)gm * NH + gn]       = __floats2bfloat162_rn(v0, v1);
                *(__nv_bfloat162*)&g_h1b[(size_t)(gm + 8) * NH + gn] = __floats2bfloat162_rn(v2, v3);
            }
        }
    }
}

// logits = h1 @ w2 + b2 ; softmax over 2 (h1 in bf16)
__global__ void fc2_softmax_k(const float* __restrict__ w2,
                              const float* __restrict__ b2,
                              float* __restrict__ out) {
    int gw = (blockIdx.x * blockDim.x + threadIdx.x) >> 5;
    int lane = threadIdx.x & 31;
    int nw = (gridDim.x * blockDim.x) >> 5;
    for (int r = gw; r < RWS; r += nw) {
        const __nv_bfloat162* h2 = (const __nv_bfloat162*)(g_h1b + (size_t)r * NH);
        float s0 = 0.f, s1 = 0.f;
        #pragma unroll
        for (int i = lane; i < NH / 2; i += 32) {
            float2 v = __bfloat1622float2(h2[i]);
            s0 += v.x * w2[4 * i]     + v.y * w2[4 * i + 2];
            s1 += v.x * w2[4 * i + 1] + v.y * w2[4 * i + 3];
        }
        #pragma unroll
        for (int o = 16; o; o >>= 1) {
            s0 += __shfl_xor_sync(0xffffffffu, s0, o);
            s1 += __shfl_xor_sync(0xffffffffu, s1, o);
        }
        if (lane == 0) {
            float l0 = s0 + b2[0], l1 = s1 + b2[1];
            float m = fmaxf(l0, l1);
            float e0 = expf(l0 - m), e1 = expf(l1 - m);
            float inv = 1.f / (e0 + e1);
            out[2 * r] = e0 * inv;
            out[2 * r + 1] = e1 * inv;
        }
    }
}

// ---------------- launch ----------------
extern "C" void kernel_launch(void* const* d_in, const int* in_sizes, int n_in,
                              void* d_out, int out_size) {
    const int*   indexes  = (const int*)d_in[0];
    const float* features = (const float*)d_in[1];
    const int*   labels   = (const int*)d_in[2];
    const int*   nbr      = (const int*)d_in[3];
    const float* conv_w   = (const float*)d_in[4];
    const float* conv_b   = (const float*)d_in[5];
    const float* w1       = (const float*)d_in[6];
    const float* b1       = (const float*)d_in[7];
    const float* pa       = (const float*)d_in[8];
    const float* w2       = (const float*)d_in[9];
    const float* b2       = (const float*)d_in[10];
    float* out = (float*)d_out;

    const int MGEMM_SMEM = 8 * 16384;   // 128 KB dynamic (4 stages x (As+Bs))
    cudaFuncSetAttribute(mgemm_k<0>, cudaFuncAttributeMaxDynamicSharedMemorySize, MGEMM_SMEM);
    cudaFuncSetAttribute(mgemm_k<1>, cudaFuncAttributeMaxDynamicSharedMemorySize, MGEMM_SMEM);

    bucket_k<<<1, 1024>>>(labels, nbr);                               // 0
    sortbucket_k<<<(NCn + 255) / 256, 256>>>();                       // 1
    convw_k<<<(CDn * NH + 255) / 256, 256>>>(conv_w, w1);             // 2
    clumean_k<<<dim3(Dn / 1024, NCn), 256>>>(features);               // 3 (profiled slot)
    build_cf_norm_k<<<RWS, 256>>>(indexes, features, labels, nbr);    // 4
    absplit_k<<<dim3(8, Bn), 256>>>();                                // 5
    maskred_k<<<Bn, 256>>>(labels, nbr);                              // 6
    center_k<<<RWS, 256>>>();                                         // 7
    bagg_k<<<dim3(Dn / 128, Bn), 128>>>();                            // 8
    mgemm_k<0><<<dim3(NH / 128, RWS / 128), 256, MGEMM_SMEM>>>(conv_b, nullptr);
    mgemm_k<1><<<dim3(NH / 128, RWS / 128), 256, MGEMM_SMEM>>>(b1, pa);
    fc2_softmax_k<<<64, 256>>>(w2, b2, out);
}

// round 11
// speedup vs baseline: 1.4237x; 1.4237x over previous
#include <cuda_runtime.h>
#include <cuda_bf16.h>
#include <stdint.h>
#include <cstdint>
#include <math.h>

// ---------------- problem constants ----------------
#define Bn   64
#define Kn   64
#define Np   32768
#define Dn   2048
#define NCn  2048
#define NH   512
#define CDn  4096      // 2*Dn
#define RWS  4096      // Bn*Kn

// ---------------- device scratch ----------------
__device__ int   g_offsets[NCn + 1];
__device__ int   g_bucket[Np];
__device__ int   g_used[NCn];
__device__ float g_clu[(size_t)NCn * Dn];          // 16 MB cluster means
__device__ float g_x[(size_t)RWS * Dn];            // 32 MB fp32 raw cf
__device__ __nv_bfloat16 g_catb[(size_t)RWS * CDn];// 32 MB bf16 [x | agg]
__device__ __nv_bfloat16 g_adjb[RWS * Kn];         // 0.5 MB bf16 masked adj
__device__ float g_apart[8 * Bn * Kn * Kn];        // 8 MB split-K partials
__device__ float g_rinv[RWS];
__device__ __nv_bfloat16 g_hb[(size_t)RWS * NH];   // 4 MB
__device__ __nv_bfloat16 g_h1b[(size_t)RWS * NH];  // 4 MB
__device__ __nv_bfloat16 g_wb[(size_t)CDn * NH];   // 4 MB
__device__ __nv_bfloat16 g_w1b[NH * NH];           // 0.5 MB

// ---------------- bucketing: count+scan+scatter + used-cluster mark ----------------
__global__ void __launch_bounds__(1024) bucket_k(const int* __restrict__ labels,
                                                 const int* __restrict__ nbr) {
    __shared__ int s[NCn];
    __shared__ int cur[NCn];
    int t = threadIdx.x;
    s[t] = 0; s[t + 1024] = 0;
    g_used[t] = 0; g_used[t + 1024] = 0;
    __syncthreads();
    for (int n = t; n < Np; n += 1024) atomicAdd(&s[labels[n]], 1);
    // mark clusters actually referenced by any sample's neighbor list
    for (int n = t; n < Bn * Kn; n += 1024) g_used[labels[nbr[n]]] = 1;
    __syncthreads();
    for (int off = 1; off < NCn; off <<= 1) {
        int v0 = (t >= off) ? s[t - off] : 0;
        int v1 = s[t + 1024 - off];
        __syncthreads();
        s[t]        += v0;
        s[t + 1024] += v1;
        __syncthreads();
    }
    int off0 = (t == 0) ? 0 : s[t - 1];
    int off1 = s[t + 1023];
    g_offsets[t]        = off0;
    g_offsets[t + 1024] = off1;
    if (t == 0) g_offsets[NCn] = s[NCn - 1];
    cur[t] = off0; cur[t + 1024] = off1;
    __syncthreads();
    for (int n = t; n < Np; n += 1024) {
        int pos = atomicAdd(&cur[labels[n]], 1);
        g_bucket[pos] = n;
    }
}

// grid-parallel per-bucket sort -> deterministic summation order
__global__ void sortbucket_k() {
    int c = blockIdx.x * blockDim.x + threadIdx.x;
    if (c >= NCn) return;
    if (!g_used[c]) return;
    int s = g_offsets[c], e = g_offsets[c + 1];
    for (int i = s + 1; i < e; i++) {
        int v = g_bucket[i];
        int j = i - 1;
        while (j >= s && g_bucket[j] > v) { g_bucket[j + 1] = g_bucket[j]; j--; }
        g_bucket[j + 1] = v;
    }
}

// ---------------- weight conversion to bf16 ----------------
__global__ void convw_k(const float* __restrict__ w, const float* __restrict__ w1) {
    int i = blockIdx.x * 256 + threadIdx.x;
    if (i < CDn * NH) g_wb[i] = __float2bfloat16(w[i]);
    if (i < NH * NH)  g_w1b[i] = __float2bfloat16(w1[i]);
}

// float4, 4 accumulator streams; only used clusters; grid (Dn/1024, NCn), 256 thr
__global__ void clumean_k(const float* __restrict__ features) {
    int c = blockIdx.y;
    if (!g_used[c]) return;
    int d4 = blockIdx.x * 256 + threadIdx.x;       // float4 column index
    int s = g_offsets[c], e = g_offsets[c + 1];
    float4 s0 = make_float4(0.f, 0.f, 0.f, 0.f);
    float4 s1 = s0, s2 = s0, s3 = s0;
    int m = s;
    for (; m + 3 < e; m += 4) {
        int i0 = g_bucket[m], i1 = g_bucket[m + 1];
        int i2 = g_bucket[m + 2], i3 = g_bucket[m + 3];
        float4 a = ((const float4*)(features + (size_t)i0 * Dn))[d4];
        float4 b = ((const float4*)(features + (size_t)i1 * Dn))[d4];
        float4 cc = ((const float4*)(features + (size_t)i2 * Dn))[d4];
        float4 dd = ((const float4*)(features + (size_t)i3 * Dn))[d4];
        s0.x += a.x;  s0.y += a.y;  s0.z += a.z;  s0.w += a.w;
        s1.x += b.x;  s1.y += b.y;  s1.z += b.z;  s1.w += b.w;
        s2.x += cc.x; s2.y += cc.y; s2.z += cc.z; s2.w += cc.w;
        s3.x += dd.x; s3.y += dd.y; s3.z += dd.z; s3.w += dd.w;
    }
    for (; m < e; m++) {
        float4 a = ((const float4*)(features + (size_t)g_bucket[m] * Dn))[d4];
        s0.x += a.x; s0.y += a.y; s0.z += a.z; s0.w += a.w;
    }
    float4 sum;
    sum.x = (s0.x + s1.x) + (s2.x + s3.x);
    sum.y = (s0.y + s1.y) + (s2.y + s3.y);
    sum.z = (s0.z + s1.z) + (s2.z + s3.z);
    sum.w = (s0.w + s1.w) + (s2.w + s3.w);
    float inv = 1.f / fmaxf((float)(e - s), 1.f);
    sum.x *= inv; sum.y *= inv; sum.z *= inv; sum.w *= inv;
    ((float4*)(g_clu + (size_t)c * Dn))[d4] = sum;
}

// ---------------- cf build + fused row-norm ----------------
__global__ void build_cf_norm_k(const int* __restrict__ indexes,
                                const float* __restrict__ features,
                                const int* __restrict__ labels,
                                const int* __restrict__ nbr) {
    int r = blockIdx.x, t = threadIdx.x;
    int b = r >> 6, k = r & 63;
    const float* src;
    if (k == 0) src = features + (size_t)indexes[b] * Dn;
    else        src = g_clu + (size_t)labels[nbr[r]] * Dn;
    const float4* s4 = (const float4*)src;
    float4* d4 = (float4*)(g_x + (size_t)r * Dn);
    float s = 0.f;
    #pragma unroll
    for (int i = t; i < Dn / 4; i += 256) {
        float4 v = s4[i];
        d4[i] = v;
        s += v.x * v.x + v.y * v.y + v.z * v.z + v.w * v.w;
    }
    __shared__ float red[8];
    #pragma unroll
    for (int o = 16; o; o >>= 1) s += __shfl_xor_sync(0xffffffffu, s, o);
    if ((t & 31) == 0) red[t >> 5] = s;
    __syncthreads();
    if (t < 8) {
        float v = red[t];
        #pragma unroll
        for (int o = 4; o; o >>= 1) v += __shfl_xor_sync(0xffu, v, o);
        if (t == 0) g_rinv[r] = 1.f / sqrtf(v);
    }
}

// ---------------- tensor-core helpers ----------------
__device__ __forceinline__ void ldsm4(unsigned* r, unsigned a) {
    asm volatile("ldmatrix.sync.aligned.m8n8.x4.shared.b16 {%0,%1,%2,%3}, [%4];"
        : "=r"(r[0]), "=r"(r[1]), "=r"(r[2]), "=r"(r[3]) : "r"(a));
}
__device__ __forceinline__ void ldsm4t(unsigned* r, unsigned a) {
    asm volatile("ldmatrix.sync.aligned.m8n8.x4.trans.shared.b16 {%0,%1,%2,%3}, [%4];"
        : "=r"(r[0]), "=r"(r[1]), "=r"(r[2]), "=r"(r[3]) : "r"(a));
}
__device__ __forceinline__ void mma16816(float* c, const unsigned* a, unsigned b0, unsigned b1) {
    asm volatile("mma.sync.aligned.m16n8k16.row.col.f32.bf16.bf16.f32 "
        "{%0,%1,%2,%3}, {%4,%5,%6,%7}, {%8,%9}, {%0,%1,%2,%3};"
        : "+f"(c[0]), "+f"(c[1]), "+f"(c[2]), "+f"(c[3])
        : "r"(a[0]), "r"(a[1]), "r"(a[2]), "r"(a[3]), "r"(b0), "r"(b1));
}
__device__ __forceinline__ void cpasync16(unsigned dst, const void* src) {
    asm volatile("cp.async.cg.shared.global [%0], [%1], 16;"
        :: "r"(dst), "l"(__cvta_generic_to_global(src)));
}
__device__ __forceinline__ void cpcommit() {
    asm volatile("cp.async.commit_group;");
}

// ---------------- A partials = cf cf^T over K-chunk 256 (split-bf16 TC) ----------------
// grid (8, Bn), 256 threads; C = Xhi Xhi^T + Xhi Xlo^T + Xlo Xhi^T (fp32 acc)
__global__ void __launch_bounds__(256) absplit_k() {
    __shared__ __nv_bfloat16 Shi[2][64 * 64];
    __shared__ __nv_bfloat16 Slo[2][64 * 64];
    int chunk = blockIdx.x, b = blockIdx.y, tid = threadIdx.x;
    int lane = tid & 31, warp = tid >> 5;
    int wm = (warp & 3) * 16, wn = (warp >> 2) * 32;
    unsigned hi_u = (unsigned)__cvta_generic_to_shared(Shi);
    unsigned lo_u = (unsigned)__cvta_generic_to_shared(Slo);

    int lr = tid >> 2;             // 0..63 loader row
    int lc = (tid & 3) * 16;       // loader col base
    const float* src = g_x + (size_t)(b * 64 + lr) * Dn + chunk * 256 + lc;

    float f[16];
    float acc[4][4] = {};

    {
        const float4* p = (const float4*)src;
        #pragma unroll
        for (int i = 0; i < 4; i++) *(float4*)&f[i * 4] = p[i];
    }

    #pragma unroll
    for (int t = 0; t < 4; t++) {
        int s = t & 1;
        {
            __nv_bfloat16 h[16], l[16];
            #pragma unroll
            for (int i = 0; i < 16; i++) {
                h[i] = __float2bfloat16(f[i]);
                l[i] = __float2bfloat16(f[i] - __bfloat162float(h[i]));
            }
            int c0 = lc >> 3;
            #pragma unroll
            for (int half = 0; half < 2; half++) {
                int c = c0 + half;
                int off = lr * 64 + ((c ^ (lr & 7)) * 8);
                uint4 uh, ul;
                __nv_bfloat162 t2;
                t2 = __nv_bfloat162(h[half * 8 + 0], h[half * 8 + 1]); uh.x = *(unsigned*)&t2;
                t2 = __nv_bfloat162(h[half * 8 + 2], h[half * 8 + 3]); uh.y = *(unsigned*)&t2;
                t2 = __nv_bfloat162(h[half * 8 + 4], h[half * 8 + 5]); uh.z = *(unsigned*)&t2;
                t2 = __nv_bfloat162(h[half * 8 + 6], h[half * 8 + 7]); uh.w = *(unsigned*)&t2;
                t2 = __nv_bfloat162(l[half * 8 + 0], l[half * 8 + 1]); ul.x = *(unsigned*)&t2;
                t2 = __nv_bfloat162(l[half * 8 + 2], l[half * 8 + 3]); ul.y = *(unsigned*)&t2;
                t2 = __nv_bfloat162(l[half * 8 + 4], l[half * 8 + 5]); ul.z = *(unsigned*)&t2;
                t2 = __nv_bfloat162(l[half * 8 + 6], l[half * 8 + 7]); ul.w = *(unsigned*)&t2;
                *(uint4*)&Shi[s][off] = uh;
                *(uint4*)&Slo[s][off] = ul;
            }
        }
        __syncthreads();
        if (t + 1 < 4) {
            const float4* p = (const float4*)(src + (t + 1) * 64);
            #pragma unroll
            for (int i = 0; i < 4; i++) *(float4*)&f[i * 4] = p[i];
        }
        unsigned base_h = hi_u + (unsigned)(s * 8192);
        unsigned base_l = lo_u + (unsigned)(s * 8192);
        #pragma unroll
        for (int k16 = 0; k16 < 4; k16++) {
            unsigned ahi[4], alo[4], bh[2][4], bl[2][4];
            int ac = k16 * 2 + (lane >> 4);
            int arow = wm + (lane & 15);
            unsigned aoff = (unsigned)((arow * 64 + ((ac ^ (arow & 7)) * 8)) * 2);
            ldsm4(ahi, base_h + aoff);
            ldsm4(alo, base_l + aoff);
            #pragma unroll
            for (int nt = 0; nt < 2; nt++) {
                int brow = wn + nt * 16 + (lane & 15);
                unsigned boff = (unsigned)((brow * 64 + ((ac ^ (brow & 7)) * 8)) * 2);
                ldsm4(bh[nt], base_h + boff);
                ldsm4(bl[nt], base_l + boff);
            }
            #pragma unroll
            for (int nt = 0; nt < 2; nt++) {
                mma16816(acc[nt * 2 + 0], ahi, bh[nt][0], bh[nt][2]);
                mma16816(acc[nt * 2 + 0], ahi, bl[nt][0], bl[nt][2]);
                mma16816(acc[nt * 2 + 0], alo, bh[nt][0], bh[nt][2]);
                mma16816(acc[nt * 2 + 1], ahi, bh[nt][1], bh[nt][3]);
                mma16816(acc[nt * 2 + 1], ahi, bl[nt][1], bl[nt][3]);
                mma16816(acc[nt * 2 + 1], alo, bh[nt][1], bh[nt][3]);
            }
        }
        __syncthreads();
    }

    // write partials (unscaled)
    float* dst = g_apart + (size_t)(chunk * Bn + b) * 4096;
    int gid = lane >> 2, tid4 = lane & 3;
    #pragma unroll
    for (int t = 0; t < 4; t++) {
        int n = wn + t * 8 + tid4 * 2;
        int m = wm + gid;
        dst[m * 64 + n]           = acc[t][0];
        dst[m * 64 + n + 1]       = acc[t][1];
        dst[(m + 8) * 64 + n]     = acc[t][2];
        dst[(m + 8) * 64 + n + 1] = acc[t][3];
    }
}

// fused: deterministic reduce of 8 partials (+/5) -> keep + mutual top-5 -> bf16 adj
__global__ void __launch_bounds__(256) maskred_k(const int* __restrict__ labels,
                                                 const int* __restrict__ nbr) {
    __shared__ float As[64][65];
    __shared__ unsigned long long rm[64];
    __shared__ int lab[64];
    __shared__ int keep[64];
    int b = blockIdx.x, t = threadIdx.x;   // 256 threads
    for (int loc = t; loc < 4096; loc += 256) {
        float s = 0.f;
        #pragma unroll
        for (int c = 0; c < 8; c++) s += g_apart[(size_t)(c * Bn + b) * 4096 + loc];
        As[loc >> 6][loc & 63] = s * 0.2f;
    }
    if (t < 64) lab[t] = labels[nbr[b * 64 + t]];
    __syncthreads();
    if (t < 64) {
        int dup = 0;
        for (int j = 0; j < t; j++) dup |= (lab[j] == lab[t]);
        keep[t] = !dup;
        unsigned long long sel = 0ULL;
        for (int r = 0; r < 5; r++) {
            float best = -3.4e38f; int bi = 0;
            for (int j = 0; j < 64; j++) {
                float v = As[t][j];
                if (!((sel >> j) & 1ULL) && v > best) { best = v; bi = j; }
            }
            sel |= 1ULL << bi;
        }
        rm[t] = sel;
    }
    __syncthreads();
    if (t < 64) {
        bool kt = keep[t];
        for (int j = 0; j < 64; j++) {
            bool mm = kt && keep[j] && ((rm[t] >> j) & 1ULL) && ((rm[j] >> t) & 1ULL);
            g_adjb[(b * 64 + t) * 64 + j] = __float2bfloat16(mm ? As[t][j] : 0.f);
        }
    }
}

// x = cf/||cf|| - q, vectorized; row 0 cancels exactly
__global__ void center_k() {
    int r = blockIdx.x, t = threadIdx.x;
    int b = r >> 6;
    float rv = g_rinv[r];
    float qv = g_rinv[b * 64];
    const float4* xr4 = (const float4*)(g_x + (size_t)r * Dn);
    const float4* xq4 = (const float4*)(g_x + (size_t)(b * 64) * Dn);
    #pragma unroll
    for (int i = t; i < Dn / 4; i += 256) {
        float4 a = xr4[i], q = xq4[i];
        __nv_bfloat162 p0 = __floats2bfloat162_rn(a.x * rv - q.x * qv, a.y * rv - q.y * qv);
        __nv_bfloat162 p1 = __floats2bfloat162_rn(a.z * rv - q.z * qv, a.w * rv - q.w * qv);
        uint2 u;
        u.x = *(unsigned*)&p0;
        u.y = *(unsigned*)&p1;
        *(uint2*)&g_catb[(size_t)r * CDn + i * 4] = u;
    }
}

// agg = adj @ x on tensor cores -> g_catb[:, Dn:2Dn]; grid (Dn/128, Bn), 128 thr
__global__ void __launch_bounds__(128) bagg_k() {
    __shared__ __nv_bfloat16 Aj[64 * 64];
    __shared__ __nv_bfloat16 Xs[64 * 128];
    int b = blockIdx.y, d0 = blockIdx.x * 128;
    int tid = threadIdx.x, lane = tid & 31, warp = tid >> 5;
    int wn = warp * 32;
    unsigned aj_u = (unsigned)__cvta_generic_to_shared(Aj);
    unsigned xs_u = (unsigned)__cvta_generic_to_shared(Xs);

    {
        int ar = tid >> 1, ac0 = (tid & 1) * 4;
        const __nv_bfloat16* src = g_adjb + (size_t)(b * 64 + ar) * 64 + ac0 * 8;
        #pragma unroll
        for (int i = 0; i < 4; i++) {
            uint4 v = *(const uint4*)(src + i * 8);
            int c = ac0 + i;
            *(uint4*)(Aj + ar * 64 + ((c ^ (ar & 7)) * 8)) = v;
        }
    }
    {
        int br = tid >> 2, bc0 = (tid & 3) * 4;
        #pragma unroll
        for (int h = 0; h < 64; h += 32) {
            int row = br + h;
            const __nv_bfloat16* src = g_catb + (size_t)(b * 64 + row) * CDn + d0 + bc0 * 8;
            #pragma unroll
            for (int i = 0; i < 4; i++) {
                uint4 v = *(const uint4*)(src + i * 8);
                int c = bc0 + i;
                int cs = (c & 8) | ((c & 7) ^ (row & 7));
                *(uint4*)(Xs + row * 128 + cs * 8) = v;
            }
        }
    }
    __syncthreads();

    float acc[4][4][4] = {};
    #pragma unroll
    for (int k16 = 0; k16 < 4; k16++) {
        unsigned afr[4][4], bfr[2][4];
        #pragma unroll
        for (int mi = 0; mi < 4; mi++) {
            int row = mi * 16 + (lane & 15);
            int c = k16 * 2 + (lane >> 4);
            ldsm4(afr[mi], aj_u + (row * 64 + ((c ^ (row & 7)) * 8)) * 2);
        }
        #pragma unroll
        for (int ni = 0; ni < 2; ni++) {
            int krow = k16 * 16 + (lane & 15);
            int c = (wn >> 3) + ni * 2 + (lane >> 4);
            int cs = (c & 8) | ((c & 7) ^ (krow & 7));
            ldsm4t(bfr[ni], xs_u + (krow * 128 + cs * 8) * 2);
        }
        #pragma unroll
        for (int mi = 0; mi < 4; mi++)
            #pragma unroll
            for (int ni = 0; ni < 2; ni++) {
                mma16816(acc[mi][ni * 2],     afr[mi], bfr[ni][0], bfr[ni][1]);
                mma16816(acc[mi][ni * 2 + 1], afr[mi], bfr[ni][2], bfr[ni][3]);
            }
    }
    int rr = lane >> 2, cc = (lane & 3) * 2;
    #pragma unroll
    for (int mi = 0; mi < 4; mi++) {
        int gm = mi * 16 + rr;
        #pragma unroll
        for (int ni = 0; ni < 4; ni++) {
            int gn = wn + ni * 8 + cc;
            size_t base0 = (size_t)(b * 64 + gm) * CDn + Dn + d0 + gn;
            size_t base1 = (size_t)(b * 64 + gm + 8) * CDn + Dn + d0 + gn;
            *(__nv_bfloat162*)&g_catb[base0] = __floats2bfloat162_rn(acc[mi][ni][0], acc[mi][ni][1]);
            *(__nv_bfloat162*)&g_catb[base1] = __floats2bfloat162_rn(acc[mi][ni][2], acc[mi][ni][3]);
        }
    }
}

// ---------------- 4-stage pipelined bf16 tensor-core GEMMs ----------------
// MODE 0: h  = relu(catb @ wb + conv_b)  -> g_hb  (bf16), K=4096
// MODE 1: h1 = prelu(hb @ w1b + b1, pa)  -> g_h1b (bf16), K=512
template <int MODE>
__global__ void __launch_bounds__(256) mgemm_k(const float* __restrict__ bias,
                                               const float* __restrict__ pa) {
    constexpr int Kd = (MODE == 0) ? CDn : NH;
    constexpr int nk = Kd / 64;
    const __nv_bfloat16* A = (MODE == 0) ? g_catb : g_hb;
    const __nv_bfloat16* W = (MODE == 0) ? g_wb : g_w1b;
    extern __shared__ __nv_bfloat16 smem[];
    int tid = threadIdx.x;
    int lane = tid & 31, warp = tid >> 5;
    int wm = (warp & 3) * 32, wn = (warp >> 2) * 64;
    int m0 = blockIdx.y * 128, n0 = blockIdx.x * 128;
    unsigned as_u = (unsigned)__cvta_generic_to_shared(smem);
    unsigned bs_u = as_u + 4 * 16384;

    int ar = tid >> 1, ac0 = (tid & 1) * 4;
    int br = tid >> 2, bc0 = (tid & 3) * 4;
    const __nv_bfloat16* Ag = A + (size_t)(m0 + ar) * Kd + ac0 * 8;
    const __nv_bfloat16* Wg = W + (size_t)br * NH + n0 + bc0 * 8;

    auto issue = [&](int it) {
        int s = it & 3;
        int k0 = it * 64;
        unsigned as_s = as_u + (unsigned)(s * 16384);
        unsigned bs_s = bs_u + (unsigned)(s * 16384);
        #pragma unroll
        for (int i = 0; i < 4; i++) {
            int c = ac0 + i;
            cpasync16(as_s + (unsigned)((ar * 64 + ((c ^ (ar & 7)) * 8)) * 2),
                      Ag + k0 + i * 8);
        }
        #pragma unroll
        for (int i = 0; i < 4; i++) {
            int c = bc0 + i;
            int cs = (c & 8) | ((c & 7) ^ (br & 7));
            cpasync16(bs_s + (unsigned)((br * 128 + cs * 8) * 2),
                      Wg + (size_t)k0 * NH + i * 8);
        }
        cpcommit();
    };

    float acc[2][8][4] = {};
    issue(0); issue(1); issue(2);
    for (int it = 0; it < nk; it++) {
        int s = it & 3;
        asm volatile("cp.async.wait_group 2;");
        __syncthreads();
        if (it + 3 < nk) issue(it + 3);
        unsigned as_s = as_u + (unsigned)(s * 16384);
        unsigned bs_s = bs_u + (unsigned)(s * 16384);
        #pragma unroll
        for (int k16 = 0; k16 < 4; k16++) {
            unsigned afr[2][4], bfr[4][4];
            #pragma unroll
            for (int mi = 0; mi < 2; mi++) {
                int row = wm + mi * 16 + (lane & 15);
                int c = k16 * 2 + (lane >> 4);
                ldsm4(afr[mi], as_s + (row * 64 + ((c ^ (row & 7)) * 8)) * 2);
            }
            #pragma unroll
            for (int ni = 0; ni < 4; ni++) {
                int krow = k16 * 16 + (lane & 15);
                int c = (wn >> 3) + ni * 2 + (lane >> 4);
                int cs = (c & 8) | ((c & 7) ^ (krow & 7));
                ldsm4t(bfr[ni], bs_s + (krow * 128 + cs * 8) * 2);
            }
            #pragma unroll
            for (int mi = 0; mi < 2; mi++)
                #pragma unroll
                for (int ni = 0; ni < 4; ni++) {
                    mma16816(acc[mi][ni * 2],     afr[mi], bfr[ni][0], bfr[ni][1]);
                    mma16816(acc[mi][ni * 2 + 1], afr[mi], bfr[ni][2], bfr[ni][3]);
                }
        }
    }

    int rr = lane >> 2, cc = (lane & 3) * 2;
    #pragma unroll
    for (int mi = 0; mi < 2; mi++) {
        int gm = m0 + wm + mi * 16 + rr;
        #pragma unroll
        for (int ni = 0; ni < 8; ni++) {
            int gn = n0 + wn + ni * 8 + cc;
            float b0 = bias[gn], b1 = bias[gn + 1];
            float v0 = acc[mi][ni][0] + b0;
            float v1 = acc[mi][ni][1] + b1;
            float v2 = acc[mi][ni][2] + b0;
            float v3 = acc[mi][ni][3] + b1;
            if (MODE == 0) {
                v0 = fmaxf(v0, 0.f); v1 = fmaxf(v1, 0.f);
                v2 = fmaxf(v2, 0.f); v3 = fmaxf(v3, 0.f);
                *(__nv_bfloat162*)&g_hb[(size_t)gm * NH + gn]       = __floats2bfloat162_rn(v0, v1);
                *(__nv_bfloat162*)&g_hb[(size_t)(gm + 8) * NH + gn] = __floats2bfloat162_rn(v2, v3);
            } else {
                float p0 = pa[gn], p1 = pa[gn + 1];
                v0 = (v0 > 0.f) ? v0 : p0 * v0;
                v1 = (v1 > 0.f) ? v1 : p1 * v1;
                v2 = (v2 > 0.f) ? v2 : p0 * v2;
                v3 = (v3 > 0.f) ? v3 : p1 * v3;
                *(__nv_bfloat162*)&g_h1b[(size_t)gm * NH + gn]       = __floats2bfloat162_rn(v0, v1);
                *(__nv_bfloat162*)&g_h1b[(size_t)(gm + 8) * NH + gn] = __floats2bfloat162_rn(v2, v3);
            }
        }
    }
}

// logits = h1 @ w2 + b2 ; softmax over 2 (h1 in bf16)
__global__ void fc2_softmax_k(const float* __restrict__ w2,
                              const float* __restrict__ b2,
                              float* __restrict__ out) {
    int gw = (blockIdx.x * blockDim.x + threadIdx.x) >> 5;
    int lane = threadIdx.x & 31;
    int nw = (gridDim.x * blockDim.x) >> 5;
    for (int r = gw; r < RWS; r += nw) {
        const __nv_bfloat162* h2 = (const __nv_bfloat162*)(g_h1b + (size_t)r * NH);
        float s0 = 0.f, s1 = 0.f;
        #pragma unroll
        for (int i = lane; i < NH / 2; i += 32) {
            float2 v = __bfloat1622float2(h2[i]);
            s0 += v.x * w2[4 * i]     + v.y * w2[4 * i + 2];
            s1 += v.x * w2[4 * i + 1] + v.y * w2[4 * i + 3];
        }
        #pragma unroll
        for (int o = 16; o; o >>= 1) {
            s0 += __shfl_xor_sync(0xffffffffu, s0, o);
            s1 += __shfl_xor_sync(0xffffffffu, s1, o);
        }
        if (lane == 0) {
            float l0 = s0 + b2[0], l1 = s1 + b2[1];
            float m = fmaxf(l0, l1);
            float e0 = expf(l0 - m), e1 = expf(l1 - m);
            float inv = 1.f / (e0 + e1);
            out[2 * r] = e0 * inv;
            out[2 * r + 1] = e1 * inv;
        }
    }
}

// ---------------- launch ----------------
extern "C" void kernel_launch(void* const* d_in, const int* in_sizes, int n_in,
                              void* d_out, int out_size) {
    const int*   indexes  = (const int*)d_in[0];
    const float* features = (const float*)d_in[1];
    const int*   labels   = (const int*)d_in[2];
    const int*   nbr      = (const int*)d_in[3];
    const float* conv_w   = (const float*)d_in[4];
    const float* conv_b   = (const float*)d_in[5];
    const float* w1       = (const float*)d_in[6];
    const float* b1       = (const float*)d_in[7];
    const float* pa       = (const float*)d_in[8];
    const float* w2       = (const float*)d_in[9];
    const float* b2       = (const float*)d_in[10];
    float* out = (float*)d_out;

    const int MGEMM_SMEM = 8 * 16384;   // 128 KB dynamic (4 stages x (As+Bs))
    cudaFuncSetAttribute(mgemm_k<0>, cudaFuncAttributeMaxDynamicSharedMemorySize, MGEMM_SMEM);
    cudaFuncSetAttribute(mgemm_k<1>, cudaFuncAttributeMaxDynamicSharedMemorySize, MGEMM_SMEM);

    bucket_k<<<1, 1024>>>(labels, nbr);                               // 0
    sortbucket_k<<<(NCn + 255) / 256, 256>>>();                       // 1
    convw_k<<<(CDn * NH + 255) / 256, 256>>>(conv_w, w1);             // 2
    clumean_k<<<dim3(Dn / 1024, NCn), 256>>>(features);               // 3 (profiled slot)
    build_cf_norm_k<<<RWS, 256>>>(indexes, features, labels, nbr);    // 4
    absplit_k<<<dim3(8, Bn), 256>>>();                                // 5
    maskred_k<<<Bn, 256>>>(labels, nbr);                              // 6
    center_k<<<RWS, 256>>>();                                         // 7
    bagg_k<<<dim3(Dn / 128, Bn), 128>>>();                            // 8
    mgemm_k<0><<<dim3(NH / 128, RWS / 128), 256, MGEMM_SMEM>>>(conv_b, nullptr);
    mgemm_k<1><<<dim3(NH / 128, RWS / 128), 256, MGEMM_SMEM>>>(b1, pa);
    fc2_softmax_k<<<64, 256>>>(w2, b2, out);
}

// round 12
// speedup vs baseline: 1.4437x; 1.0141x over previous
#include <cuda_runtime.h>
#include <cuda_bf16.h>
#include <stdint.h>
#include <cstdint>
#include <math.h>

// ---------------- problem constants ----------------
#define Bn   64
#define Kn   64
#define Np   32768
#define Dn   2048
#define NCn  2048
#define NH   512
#define CDn  4096      // 2*Dn
#define RWS  4096      // Bn*Kn

// ---------------- device scratch ----------------
__device__ int   g_offsets[NCn + 1];
__device__ int   g_bucket[Np];
__device__ int   g_used[NCn];
__device__ float g_clu[(size_t)NCn * Dn];          // 16 MB cluster means
__device__ float g_x[(size_t)RWS * Dn];            // 32 MB fp32 raw cf
__device__ __nv_bfloat16 g_catb[(size_t)RWS * CDn];// 32 MB bf16 [x | agg]
__device__ __nv_bfloat16 g_adjb[RWS * Kn];         // 0.5 MB bf16 masked adj
__device__ float g_apart[8 * Bn * Kn * Kn];        // 8 MB split-K partials
__device__ float g_rinv[RWS];
__device__ __nv_bfloat16 g_hb[(size_t)RWS * NH];   // 4 MB
__device__ __nv_bfloat16 g_h1b[(size_t)RWS * NH];  // 4 MB
__device__ __nv_bfloat16 g_wb[(size_t)CDn * NH];   // 4 MB
__device__ __nv_bfloat16 g_w1b[NH * NH];           // 0.5 MB

// ---------------- bucketing: count+scan+scatter + used-cluster mark ----------------
__global__ void __launch_bounds__(1024) bucket_k(const int* __restrict__ labels,
                                                 const int* __restrict__ nbr) {
    __shared__ int s[NCn];
    __shared__ int cur[NCn];
    int t = threadIdx.x;
    s[t] = 0; s[t + 1024] = 0;
    g_used[t] = 0; g_used[t + 1024] = 0;
    __syncthreads();
    for (int n = t; n < Np; n += 1024) atomicAdd(&s[labels[n]], 1);
    for (int n = t; n < Bn * Kn; n += 1024) g_used[labels[nbr[n]]] = 1;
    __syncthreads();
    for (int off = 1; off < NCn; off <<= 1) {
        int v0 = (t >= off) ? s[t - off] : 0;
        int v1 = s[t + 1024 - off];
        __syncthreads();
        s[t]        += v0;
        s[t + 1024] += v1;
        __syncthreads();
    }
    int off0 = (t == 0) ? 0 : s[t - 1];
    int off1 = s[t + 1023];
    g_offsets[t]        = off0;
    g_offsets[t + 1024] = off1;
    if (t == 0) g_offsets[NCn] = s[NCn - 1];
    cur[t] = off0; cur[t + 1024] = off1;
    __syncthreads();
    for (int n = t; n < Np; n += 1024) {
        int pos = atomicAdd(&cur[labels[n]], 1);
        g_bucket[pos] = n;
    }
}

// grid-parallel per-bucket sort -> deterministic summation order
__global__ void sortbucket_k() {
    int c = blockIdx.x * blockDim.x + threadIdx.x;
    if (c >= NCn) return;
    if (!g_used[c]) return;
    int s = g_offsets[c], e = g_offsets[c + 1];
    for (int i = s + 1; i < e; i++) {
        int v = g_bucket[i];
        int j = i - 1;
        while (j >= s && g_bucket[j] > v) { g_bucket[j + 1] = g_bucket[j]; j--; }
        g_bucket[j + 1] = v;
    }
}

// ---------------- weight conversion to bf16 ----------------
__global__ void convw_k(const float* __restrict__ w, const float* __restrict__ w1) {
    int i = blockIdx.x * 256 + threadIdx.x;
    if (i < CDn * NH) g_wb[i] = __float2bfloat16(w[i]);
    if (i < NH * NH)  g_w1b[i] = __float2bfloat16(w1[i]);
}

// float4, 4 accumulator streams; only used clusters; grid (Dn/1024, NCn), 256 thr
__global__ void clumean_k(const float* __restrict__ features) {
    int c = blockIdx.y;
    if (!g_used[c]) return;
    int d4 = blockIdx.x * 256 + threadIdx.x;       // float4 column index
    int s = g_offsets[c], e = g_offsets[c + 1];
    float4 s0 = make_float4(0.f, 0.f, 0.f, 0.f);
    float4 s1 = s0, s2 = s0, s3 = s0;
    int m = s;
    for (; m + 3 < e; m += 4) {
        int i0 = g_bucket[m], i1 = g_bucket[m + 1];
        int i2 = g_bucket[m + 2], i3 = g_bucket[m + 3];
        float4 a = ((const float4*)(features + (size_t)i0 * Dn))[d4];
        float4 b = ((const float4*)(features + (size_t)i1 * Dn))[d4];
        float4 cc = ((const float4*)(features + (size_t)i2 * Dn))[d4];
        float4 dd = ((const float4*)(features + (size_t)i3 * Dn))[d4];
        s0.x += a.x;  s0.y += a.y;  s0.z += a.z;  s0.w += a.w;
        s1.x += b.x;  s1.y += b.y;  s1.z += b.z;  s1.w += b.w;
        s2.x += cc.x; s2.y += cc.y; s2.z += cc.z; s2.w += cc.w;
        s3.x += dd.x; s3.y += dd.y; s3.z += dd.z; s3.w += dd.w;
    }
    for (; m < e; m++) {
        float4 a = ((const float4*)(features + (size_t)g_bucket[m] * Dn))[d4];
        s0.x += a.x; s0.y += a.y; s0.z += a.z; s0.w += a.w;
    }
    float4 sum;
    sum.x = (s0.x + s1.x) + (s2.x + s3.x);
    sum.y = (s0.y + s1.y) + (s2.y + s3.y);
    sum.z = (s0.z + s1.z) + (s2.z + s3.z);
    sum.w = (s0.w + s1.w) + (s2.w + s3.w);
    float inv = 1.f / fmaxf((float)(e - s), 1.f);
    sum.x *= inv; sum.y *= inv; sum.z *= inv; sum.w *= inv;
    ((float4*)(g_clu + (size_t)c * Dn))[d4] = sum;
}

// ---------------- cf build + fused row-norm ----------------
__global__ void build_cf_norm_k(const int* __restrict__ indexes,
                                const float* __restrict__ features,
                                const int* __restrict__ labels,
                                const int* __restrict__ nbr) {
    int r = blockIdx.x, t = threadIdx.x;
    int b = r >> 6, k = r & 63;
    const float* src;
    if (k == 0) src = features + (size_t)indexes[b] * Dn;
    else        src = g_clu + (size_t)labels[nbr[r]] * Dn;
    const float4* s4 = (const float4*)src;
    float4* d4 = (float4*)(g_x + (size_t)r * Dn);
    float s = 0.f;
    #pragma unroll
    for (int i = t; i < Dn / 4; i += 256) {
        float4 v = s4[i];
        d4[i] = v;
        s += v.x * v.x + v.y * v.y + v.z * v.z + v.w * v.w;
    }
    __shared__ float red[8];
    #pragma unroll
    for (int o = 16; o; o >>= 1) s += __shfl_xor_sync(0xffffffffu, s, o);
    if ((t & 31) == 0) red[t >> 5] = s;
    __syncthreads();
    if (t < 8) {
        float v = red[t];
        #pragma unroll
        for (int o = 4; o; o >>= 1) v += __shfl_xor_sync(0xffu, v, o);
        if (t == 0) g_rinv[r] = 1.f / sqrtf(v);
    }
}

// ---------------- tensor-core helpers ----------------
__device__ __forceinline__ void ldsm4(unsigned* r, unsigned a) {
    asm volatile("ldmatrix.sync.aligned.m8n8.x4.shared.b16 {%0,%1,%2,%3}, [%4];"
        : "=r"(r[0]), "=r"(r[1]), "=r"(r[2]), "=r"(r[3]) : "r"(a));
}
__device__ __forceinline__ void ldsm4t(unsigned* r, unsigned a) {
    asm volatile("ldmatrix.sync.aligned.m8n8.x4.trans.shared.b16 {%0,%1,%2,%3}, [%4];"
        : "=r"(r[0]), "=r"(r[1]), "=r"(r[2]), "=r"(r[3]) : "r"(a));
}
__device__ __forceinline__ void mma16816(float* c, const unsigned* a, unsigned b0, unsigned b1) {
    asm volatile("mma.sync.aligned.m16n8k16.row.col.f32.bf16.bf16.f32 "
        "{%0,%1,%2,%3}, {%4,%5,%6,%7}, {%8,%9}, {%0,%1,%2,%3};"
        : "+f"(c[0]), "+f"(c[1]), "+f"(c[2]), "+f"(c[3])
        : "r"(a[0]), "r"(a[1]), "r"(a[2]), "r"(a[3]), "r"(b0), "r"(b1));
}
__device__ __forceinline__ void cpasync16(unsigned dst, const void* src) {
    asm volatile("cp.async.cg.shared.global [%0], [%1], 16;"
        :: "r"(dst), "l"(__cvta_generic_to_global(src)));
}
__device__ __forceinline__ void cpcommit() {
    asm volatile("cp.async.commit_group;");
}

// ---------------- A partials = cf cf^T over K-chunk 256 (split-bf16 TC) ----------------
// grid (8, Bn), 256 threads; C = Xhi Xhi^T + Xhi Xlo^T + Xlo Xhi^T (fp32 acc)
__global__ void __launch_bounds__(256) absplit_k() {
    __shared__ __nv_bfloat16 Shi[2][64 * 64];
    __shared__ __nv_bfloat16 Slo[2][64 * 64];
    int chunk = blockIdx.x, b = blockIdx.y, tid = threadIdx.x;
    int lane = tid & 31, warp = tid >> 5;
    int wm = (warp & 3) * 16, wn = (warp >> 2) * 32;
    unsigned hi_u = (unsigned)__cvta_generic_to_shared(Shi);
    unsigned lo_u = (unsigned)__cvta_generic_to_shared(Slo);

    int lr = tid >> 2;             // 0..63 loader row
    int lc = (tid & 3) * 16;       // loader col base
    const float* src = g_x + (size_t)(b * 64 + lr) * Dn + chunk * 256 + lc;

    float f[16];
    float acc[4][4] = {};

    {
        const float4* p = (const float4*)src;
        #pragma unroll
        for (int i = 0; i < 4; i++) *(float4*)&f[i * 4] = p[i];
    }

    #pragma unroll
    for (int t = 0; t < 4; t++) {
        int s = t & 1;
        {
            __nv_bfloat16 h[16], l[16];
            #pragma unroll
            for (int i = 0; i < 16; i++) {
                h[i] = __float2bfloat16(f[i]);
                l[i] = __float2bfloat16(f[i] - __bfloat162float(h[i]));
            }
            int c0 = lc >> 3;
            #pragma unroll
            for (int half = 0; half < 2; half++) {
                int c = c0 + half;
                int off = lr * 64 + ((c ^ (lr & 7)) * 8);
                uint4 uh, ul;
                __nv_bfloat162 t2;
                t2 = __nv_bfloat162(h[half * 8 + 0], h[half * 8 + 1]); uh.x = *(unsigned*)&t2;
                t2 = __nv_bfloat162(h[half * 8 + 2], h[half * 8 + 3]); uh.y = *(unsigned*)&t2;
                t2 = __nv_bfloat162(h[half * 8 + 4], h[half * 8 + 5]); uh.z = *(unsigned*)&t2;
                t2 = __nv_bfloat162(h[half * 8 + 6], h[half * 8 + 7]); uh.w = *(unsigned*)&t2;
                t2 = __nv_bfloat162(l[half * 8 + 0], l[half * 8 + 1]); ul.x = *(unsigned*)&t2;
                t2 = __nv_bfloat162(l[half * 8 + 2], l[half * 8 + 3]); ul.y = *(unsigned*)&t2;
                t2 = __nv_bfloat162(l[half * 8 + 4], l[half * 8 + 5]); ul.z = *(unsigned*)&t2;
                t2 = __nv_bfloat162(l[half * 8 + 6], l[half * 8 + 7]); ul.w = *(unsigned*)&t2;
                *(uint4*)&Shi[s][off] = uh;
                *(uint4*)&Slo[s][off] = ul;
            }
        }
        __syncthreads();
        if (t + 1 < 4) {
            const float4* p = (const float4*)(src + (t + 1) * 64);
            #pragma unroll
            for (int i = 0; i < 4; i++) *(float4*)&f[i * 4] = p[i];
        }
        unsigned base_h = hi_u + (unsigned)(s * 8192);
        unsigned base_l = lo_u + (unsigned)(s * 8192);
        #pragma unroll
        for (int k16 = 0; k16 < 4; k16++) {
            unsigned ahi[4], alo[4], bh[2][4], bl[2][4];
            int ac = k16 * 2 + (lane >> 4);
            int arow = wm + (lane & 15);
            unsigned aoff = (unsigned)((arow * 64 + ((ac ^ (arow & 7)) * 8)) * 2);
            ldsm4(ahi, base_h + aoff);
            ldsm4(alo, base_l + aoff);
            #pragma unroll
            for (int nt = 0; nt < 2; nt++) {
                int brow = wn + nt * 16 + (lane & 15);
                unsigned boff = (unsigned)((brow * 64 + ((ac ^ (brow & 7)) * 8)) * 2);
                ldsm4(bh[nt], base_h + boff);
                ldsm4(bl[nt], base_l + boff);
            }
            #pragma unroll
            for (int nt = 0; nt < 2; nt++) {
                mma16816(acc[nt * 2 + 0], ahi, bh[nt][0], bh[nt][2]);
                mma16816(acc[nt * 2 + 0], ahi, bl[nt][0], bl[nt][2]);
                mma16816(acc[nt * 2 + 0], alo, bh[nt][0], bh[nt][2]);
                mma16816(acc[nt * 2 + 1], ahi, bh[nt][1], bh[nt][3]);
                mma16816(acc[nt * 2 + 1], ahi, bl[nt][1], bl[nt][3]);
                mma16816(acc[nt * 2 + 1], alo, bh[nt][1], bh[nt][3]);
            }
        }
        __syncthreads();
    }

    // write partials (unscaled)
    float* dst = g_apart + (size_t)(chunk * Bn + b) * 4096;
    int gid = lane >> 2, tid4 = lane & 3;
    #pragma unroll
    for (int t = 0; t < 4; t++) {
        int n = wn + t * 8 + tid4 * 2;
        int m = wm + gid;
        dst[m * 64 + n]           = acc[t][0];
        dst[m * 64 + n + 1]       = acc[t][1];
        dst[(m + 8) * 64 + n]     = acc[t][2];
        dst[(m + 8) * 64 + n + 1] = acc[t][3];
    }
}

// fused: deterministic reduce of 8 partials (+/5) -> keep + mutual top-5 -> bf16 adj
__global__ void __launch_bounds__(256) maskred_k(const int* __restrict__ labels,
                                                 const int* __restrict__ nbr) {
    __shared__ float As[64][65];
    __shared__ unsigned long long rm[64];
    __shared__ int lab[64];
    __shared__ int keep[64];
    int b = blockIdx.x, t = threadIdx.x;   // 256 threads
    for (int loc = t; loc < 4096; loc += 256) {
        float s = 0.f;
        #pragma unroll
        for (int c = 0; c < 8; c++) s += g_apart[(size_t)(c * Bn + b) * 4096 + loc];
        As[loc >> 6][loc & 63] = s * 0.2f;
    }
    if (t < 64) lab[t] = labels[nbr[b * 64 + t]];
    __syncthreads();
    if (t < 64) {
        int dup = 0;
        for (int j = 0; j < t; j++) dup |= (lab[j] == lab[t]);
        keep[t] = !dup;
        unsigned long long sel = 0ULL;
        for (int r = 0; r < 5; r++) {
            float best = -3.4e38f; int bi = 0;
            for (int j = 0; j < 64; j++) {
                float v = As[t][j];
                if (!((sel >> j) & 1ULL) && v > best) { best = v; bi = j; }
            }
            sel |= 1ULL << bi;
        }
        rm[t] = sel;
    }
    __syncthreads();
    if (t < 64) {
        bool kt = keep[t];
        for (int j = 0; j < 64; j++) {
            bool mm = kt && keep[j] && ((rm[t] >> j) & 1ULL) && ((rm[j] >> t) & 1ULL);
            g_adjb[(b * 64 + t) * 64 + j] = __float2bfloat16(mm ? As[t][j] : 0.f);
        }
    }
}

// x = cf/||cf|| - q, vectorized; row 0 cancels exactly
__global__ void center_k() {
    int r = blockIdx.x, t = threadIdx.x;
    int b = r >> 6;
    float rv = g_rinv[r];
    float qv = g_rinv[b * 64];
    const float4* xr4 = (const float4*)(g_x + (size_t)r * Dn);
    const float4* xq4 = (const float4*)(g_x + (size_t)(b * 64) * Dn);
    #pragma unroll
    for (int i = t; i < Dn / 4; i += 256) {
        float4 a = xr4[i], q = xq4[i];
        __nv_bfloat162 p0 = __floats2bfloat162_rn(a.x * rv - q.x * qv, a.y * rv - q.y * qv);
        __nv_bfloat162 p1 = __floats2bfloat162_rn(a.z * rv - q.z * qv, a.w * rv - q.w * qv);
        uint2 u;
        u.x = *(unsigned*)&p0;
        u.y = *(unsigned*)&p1;
        *(uint2*)&g_catb[(size_t)r * CDn + i * 4] = u;
    }
}

// agg = adj @ x on tensor cores -> g_catb[:, Dn:2Dn]; grid (Dn/128, Bn), 128 thr
__global__ void __launch_bounds__(128) bagg_k() {
    __shared__ __nv_bfloat16 Aj[64 * 64];
    __shared__ __nv_bfloat16 Xs[64 * 128];
    int b = blockIdx.y, d0 = blockIdx.x * 128;
    int tid = threadIdx.x, lane = tid & 31, warp = tid >> 5;
    int wn = warp * 32;
    unsigned aj_u = (unsigned)__cvta_generic_to_shared(Aj);
    unsigned xs_u = (unsigned)__cvta_generic_to_shared(Xs);

    {
        int ar = tid >> 1, ac0 = (tid & 1) * 4;
        const __nv_bfloat16* src = g_adjb + (size_t)(b * 64 + ar) * 64 + ac0 * 8;
        #pragma unroll
        for (int i = 0; i < 4; i++) {
            uint4 v = *(const uint4*)(src + i * 8);
            int c = ac0 + i;
            *(uint4*)(Aj + ar * 64 + ((c ^ (ar & 7)) * 8)) = v;
        }
    }
    {
        int br = tid >> 2, bc0 = (tid & 3) * 4;
        #pragma unroll
        for (int h = 0; h < 64; h += 32) {
            int row = br + h;
            const __nv_bfloat16* src = g_catb + (size_t)(b * 64 + row) * CDn + d0 + bc0 * 8;
            #pragma unroll
            for (int i = 0; i < 4; i++) {
                uint4 v = *(const uint4*)(src + i * 8);
                int c = bc0 + i;
                int cs = (c & 8) | ((c & 7) ^ (row & 7));
                *(uint4*)(Xs + row * 128 + cs * 8) = v;
            }
        }
    }
    __syncthreads();

    float acc[4][4][4] = {};
    #pragma unroll
    for (int k16 = 0; k16 < 4; k16++) {
        unsigned afr[4][4], bfr[2][4];
        #pragma unroll
        for (int mi = 0; mi < 4; mi++) {
            int row = mi * 16 + (lane & 15);
            int c = k16 * 2 + (lane >> 4);
            ldsm4(afr[mi], aj_u + (row * 64 + ((c ^ (row & 7)) * 8)) * 2);
        }
        #pragma unroll
        for (int ni = 0; ni < 2; ni++) {
            int krow = k16 * 16 + (lane & 15);
            int c = (wn >> 3) + ni * 2 + (lane >> 4);
            int cs = (c & 8) | ((c & 7) ^ (krow & 7));
            ldsm4t(bfr[ni], xs_u + (krow * 128 + cs * 8) * 2);
        }
        #pragma unroll
        for (int mi = 0; mi < 4; mi++)
            #pragma unroll
            for (int ni = 0; ni < 2; ni++) {
                mma16816(acc[mi][ni * 2],     afr[mi], bfr[ni][0], bfr[ni][1]);
                mma16816(acc[mi][ni * 2 + 1], afr[mi], bfr[ni][2], bfr[ni][3]);
            }
    }
    int rr = lane >> 2, cc = (lane & 3) * 2;
    #pragma unroll
    for (int mi = 0; mi < 4; mi++) {
        int gm = mi * 16 + rr;
        #pragma unroll
        for (int ni = 0; ni < 4; ni++) {
            int gn = wn + ni * 8 + cc;
            size_t base0 = (size_t)(b * 64 + gm) * CDn + Dn + d0 + gn;
            size_t base1 = (size_t)(b * 64 + gm + 8) * CDn + Dn + d0 + gn;
            *(__nv_bfloat162*)&g_catb[base0] = __floats2bfloat162_rn(acc[mi][ni][0], acc[mi][ni][1]);
            *(__nv_bfloat162*)&g_catb[base1] = __floats2bfloat162_rn(acc[mi][ni][2], acc[mi][ni][3]);
        }
    }
}

// ---------------- 4-stage pipelined bf16 tensor-core GEMMs ----------------
// BM=64, BN=128, BK=64; 256 threads = 8 warps (2M x 4N), warp tile 32x32.
// MODE 0: h  = relu(catb @ wb + conv_b)  -> g_hb  (bf16), K=4096
// MODE 1: h1 = prelu(hb @ w1b + b1, pa)  -> g_h1b (bf16), K=512
template <int MODE>
__global__ void __launch_bounds__(256) mgemm_k(const float* __restrict__ bias,
                                               const float* __restrict__ pa) {
    constexpr int Kd = (MODE == 0) ? CDn : NH;
    constexpr int nk = Kd / 64;
    const __nv_bfloat16* A = (MODE == 0) ? g_catb : g_hb;
    const __nv_bfloat16* W = (MODE == 0) ? g_wb : g_w1b;
    extern __shared__ __nv_bfloat16 smem[];
    // layout: [As x4 stages of 8KB][Bs x4 stages of 16KB]
    int tid = threadIdx.x;
    int lane = tid & 31, warp = tid >> 5;
    int wm = (warp & 1) * 32, wn = (warp >> 1) * 32;
    int m0 = blockIdx.y * 64, n0 = blockIdx.x * 128;
    unsigned as_u = (unsigned)__cvta_generic_to_shared(smem);
    unsigned bs_u = as_u + 4 * 8192;

    int ar = tid >> 2, ac0 = (tid & 3) * 2;       // A: 64 rows x 8 chunks, 4 thr/row x 2 chunks
    int br = tid >> 2, bc0 = (tid & 3) * 4;       // B: 64 rows x 16 chunks, 4 thr/row x 4 chunks
    const __nv_bfloat16* Ag = A + (size_t)(m0 + ar) * Kd + ac0 * 8;
    const __nv_bfloat16* Wg = W + (size_t)br * NH + n0 + bc0 * 8;

    auto issue = [&](int it) {
        int s = it & 3;
        int k0 = it * 64;
        unsigned as_s = as_u + (unsigned)(s * 8192);
        unsigned bs_s = bs_u + (unsigned)(s * 16384);
        #pragma unroll
        for (int i = 0; i < 2; i++) {
            int c = ac0 + i;
            cpasync16(as_s + (unsigned)((ar * 64 + ((c ^ (ar & 7)) * 8)) * 2),
                      Ag + k0 + i * 8);
        }
        #pragma unroll
        for (int i = 0; i < 4; i++) {
            int c = bc0 + i;
            int cs = (c & 8) | ((c & 7) ^ (br & 7));
            cpasync16(bs_s + (unsigned)((br * 128 + cs * 8) * 2),
                      Wg + (size_t)k0 * NH + i * 8);
        }
        cpcommit();
    };

    float acc[2][4][4] = {};
    issue(0); issue(1); issue(2);
    for (int it = 0; it < nk; it++) {
        int s = it & 3;
        asm volatile("cp.async.wait_group 2;");
        __syncthreads();
        if (it + 3 < nk) issue(it + 3);
        unsigned as_s = as_u + (unsigned)(s * 8192);
        unsigned bs_s = bs_u + (unsigned)(s * 16384);
        #pragma unroll
        for (int k16 = 0; k16 < 4; k16++) {
            unsigned afr[2][4], bfr[2][4];
            #pragma unroll
            for (int mi = 0; mi < 2; mi++) {
                int row = wm + mi * 16 + (lane & 15);
                int c = k16 * 2 + (lane >> 4);
                ldsm4(afr[mi], as_s + (row * 64 + ((c ^ (row & 7)) * 8)) * 2);
            }
            #pragma unroll
            for (int ni = 0; ni < 2; ni++) {
                int krow = k16 * 16 + (lane & 15);
                int c = (wn >> 3) + ni * 2 + (lane >> 4);
                int cs = (c & 8) | ((c & 7) ^ (krow & 7));
                ldsm4t(bfr[ni], bs_s + (krow * 128 + cs * 8) * 2);
            }
            #pragma unroll
            for (int mi = 0; mi < 2; mi++)
                #pragma unroll
                for (int ni = 0; ni < 2; ni++) {
                    mma16816(acc[mi][ni * 2],     afr[mi], bfr[ni][0], bfr[ni][1]);
                    mma16816(acc[mi][ni * 2 + 1], afr[mi], bfr[ni][2], bfr[ni][3]);
                }
        }
    }

    int rr = lane >> 2, cc = (lane & 3) * 2;
    #pragma unroll
    for (int mi = 0; mi < 2; mi++) {
        int gm = m0 + wm + mi * 16 + rr;
        #pragma unroll
        for (int ni = 0; ni < 4; ni++) {
            int gn = n0 + wn + ni * 8 + cc;
            float b0 = bias[gn], b1 = bias[gn + 1];
            float v0 = acc[mi][ni][0] + b0;
            float v1 = acc[mi][ni][1] + b1;
            float v2 = acc[mi][ni][2] + b0;
            float v3 = acc[mi][ni][3] + b1;
            if (MODE == 0) {
                v0 = fmaxf(v0, 0.f); v1 = fmaxf(v1, 0.f);
                v2 = fmaxf(v2, 0.f); v3 = fmaxf(v3, 0.f);
                *(__nv_bfloat162*)&g_hb[(size_t)gm * NH + gn]       = __floats2bfloat162_rn(v0, v1);
                *(__nv_bfloat162*)&g_hb[(size_t)(gm + 8) * NH + gn] = __floats2bfloat162_rn(v2, v3);
            } else {
                float p0 = pa[gn], p1 = pa[gn + 1];
                v0 = (v0 > 0.f) ? v0 : p0 * v0;
                v1 = (v1 > 0.f) ? v1 : p1 * v1;
                v2 = (v2 > 0.f) ? v2 : p0 * v2;
                v3 = (v3 > 0.f) ? v3 : p1 * v3;
                *(__nv_bfloat162*)&g_h1b[(size_t)gm * NH + gn]       = __floats2bfloat162_rn(v0, v1);
                *(__nv_bfloat162*)&g_h1b[(size_t)(gm + 8) * NH + gn] = __floats2bfloat162_rn(v2, v3);
            }
        }
    }
}

// logits = h1 @ w2 + b2 ; softmax over 2 (h1 in bf16)
__global__ void fc2_softmax_k(const float* __restrict__ w2,
                              const float* __restrict__ b2,
                              float* __restrict__ out) {
    int gw = (blockIdx.x * blockDim.x + threadIdx.x) >> 5;
    int lane = threadIdx.x & 31;
    int nw = (gridDim.x * blockDim.x) >> 5;
    for (int r = gw; r < RWS; r += nw) {
        const __nv_bfloat162* h2 = (const __nv_bfloat162*)(g_h1b + (size_t)r * NH);
        float s0 = 0.f, s1 = 0.f;
        #pragma unroll
        for (int i = lane; i < NH / 2; i += 32) {
            float2 v = __bfloat1622float2(h2[i]);
            s0 += v.x * w2[4 * i]     + v.y * w2[4 * i + 2];
            s1 += v.x * w2[4 * i + 1] + v.y * w2[4 * i + 3];
        }
        #pragma unroll
        for (int o = 16; o; o >>= 1) {
            s0 += __shfl_xor_sync(0xffffffffu, s0, o);
            s1 += __shfl_xor_sync(0xffffffffu, s1, o);
        }
        if (lane == 0) {
            float l0 = s0 + b2[0], l1 = s1 + b2[1];
            float m = fmaxf(l0, l1);
            float e0 = expf(l0 - m), e1 = expf(l1 - m);
            float inv = 1.f / (e0 + e1);
            out[2 * r] = e0 * inv;
            out[2 * r + 1] = e1 * inv;
        }
    }
}

// ---------------- launch ----------------
extern "C" void kernel_launch(void* const* d_in, const int* in_sizes, int n_in,
                              void* d_out, int out_size) {
    const int*   indexes  = (const int*)d_in[0];
    const float* features = (const float*)d_in[1];
    const int*   labels   = (const int*)d_in[2];
    const int*   nbr      = (const int*)d_in[3];
    const float* conv_w   = (const float*)d_in[4];
    const float* conv_b   = (const float*)d_in[5];
    const float* w1       = (const float*)d_in[6];
    const float* b1       = (const float*)d_in[7];
    const float* pa       = (const float*)d_in[8];
    const float* w2       = (const float*)d_in[9];
    const float* b2       = (const float*)d_in[10];
    float* out = (float*)d_out;

    const int MGEMM_SMEM = 4 * (8192 + 16384);   // 96 KB dynamic (4 stages)
    cudaFuncSetAttribute(mgemm_k<0>, cudaFuncAttributeMaxDynamicSharedMemorySize, MGEMM_SMEM);
    cudaFuncSetAttribute(mgemm_k<1>, cudaFuncAttributeMaxDynamicSharedMemorySize, MGEMM_SMEM);

    bucket_k<<<1, 1024>>>(labels, nbr);                               // 0
    sortbucket_k<<<(NCn + 255) / 256, 256>>>();                       // 1
    convw_k<<<(CDn * NH + 255) / 256, 256>>>(conv_w, w1);             // 2
    clumean_k<<<dim3(Dn / 1024, NCn), 256>>>(features);               // 3 (profiled slot)
    build_cf_norm_k<<<RWS, 256>>>(indexes, features, labels, nbr);    // 4
    absplit_k<<<dim3(8, Bn), 256>>>();                                // 5
    maskred_k<<<Bn, 256>>>(labels, nbr);                              // 6
    center_k<<<RWS, 256>>>();                                         // 7
    bagg_k<<<dim3(Dn / 128, Bn), 128>>>();                            // 8
    mgemm_k<0><<<dim3(NH / 128, RWS / 64), 256, MGEMM_SMEM>>>(conv_b, nullptr);
    mgemm_k<1><<<dim3(NH / 128, RWS / 64), 256, MGEMM_SMEM>>>(b1, pa);
    fc2_softmax_k<<<64, 256>>>(w2, b2, out);
}

// round 13
// speedup vs baseline: 1.4624x; 1.0130x over previous
#include <cuda_runtime.h>
#include <cuda_bf16.h>
#include <stdint.h>
#include <cstdint>
#include <math.h>

// ---------------- problem constants ----------------
#define Bn   64
#define Kn   64
#define Np   32768
#define Dn   2048
#define NCn  2048
#define NH   512
#define CDn  4096      // 2*Dn
#define RWS  4096      // Bn*Kn

// ---------------- device scratch ----------------
__device__ int   g_offsets[NCn + 1];
__device__ int   g_bucket[Np];
__device__ int   g_used[NCn];
__device__ float g_clu[(size_t)NCn * Dn];          // 16 MB cluster means
__device__ float g_x[(size_t)RWS * Dn];            // 32 MB fp32 raw cf
__device__ __nv_bfloat16 g_catb[(size_t)RWS * CDn];// 32 MB bf16 [x | agg]
__device__ __nv_bfloat16 g_adjb[RWS * Kn];         // 0.5 MB bf16 masked adj
__device__ float g_apart[8 * Bn * Kn * Kn];        // 8 MB split-K partials
__device__ float g_rinv[RWS];
__device__ __nv_bfloat16 g_hb[(size_t)RWS * NH];   // 4 MB
__device__ __nv_bfloat16 g_h1b[(size_t)RWS * NH];  // 4 MB
__device__ __nv_bfloat16 g_wb[(size_t)CDn * NH];   // 4 MB
__device__ __nv_bfloat16 g_w1b[NH * NH];           // 0.5 MB

// ---------------- bucketing: count+scan+scatter + used-cluster mark ----------------
__global__ void __launch_bounds__(1024) bucket_k(const int* __restrict__ labels,
                                                 const int* __restrict__ nbr) {
    __shared__ int s[NCn];
    __shared__ int cur[NCn];
    int t = threadIdx.x;
    s[t] = 0; s[t + 1024] = 0;
    g_used[t] = 0; g_used[t + 1024] = 0;
    __syncthreads();
    for (int n = t; n < Np; n += 1024) atomicAdd(&s[labels[n]], 1);
    for (int n = t; n < Bn * Kn; n += 1024) g_used[labels[nbr[n]]] = 1;
    __syncthreads();
    for (int off = 1; off < NCn; off <<= 1) {
        int v0 = (t >= off) ? s[t - off] : 0;
        int v1 = s[t + 1024 - off];
        __syncthreads();
        s[t]        += v0;
        s[t + 1024] += v1;
        __syncthreads();
    }
    int off0 = (t == 0) ? 0 : s[t - 1];
    int off1 = s[t + 1023];
    g_offsets[t]        = off0;
    g_offsets[t + 1024] = off1;
    if (t == 0) g_offsets[NCn] = s[NCn - 1];
    cur[t] = off0; cur[t + 1024] = off1;
    __syncthreads();
    for (int n = t; n < Np; n += 1024) {
        int pos = atomicAdd(&cur[labels[n]], 1);
        g_bucket[pos] = n;
    }
}

// grid-parallel per-bucket sort -> deterministic summation order
__global__ void sortbucket_k() {
    int c = blockIdx.x * blockDim.x + threadIdx.x;
    if (c >= NCn) return;
    if (!g_used[c]) return;
    int s = g_offsets[c], e = g_offsets[c + 1];
    for (int i = s + 1; i < e; i++) {
        int v = g_bucket[i];
        int j = i - 1;
        while (j >= s && g_bucket[j] > v) { g_bucket[j + 1] = g_bucket[j]; j--; }
        g_bucket[j + 1] = v;
    }
}

// ---------------- weight conversion to bf16 ----------------
__global__ void convw_k(const float* __restrict__ w, const float* __restrict__ w1) {
    int i = blockIdx.x * 256 + threadIdx.x;
    if (i < CDn * NH) g_wb[i] = __float2bfloat16(w[i]);
    if (i < NH * NH)  g_w1b[i] = __float2bfloat16(w1[i]);
}

// float4, 4 accumulator streams; only used clusters; grid (Dn/1024, NCn), 256 thr
__global__ void clumean_k(const float* __restrict__ features) {
    int c = blockIdx.y;
    if (!g_used[c]) return;
    int d4 = blockIdx.x * 256 + threadIdx.x;       // float4 column index
    int s = g_offsets[c], e = g_offsets[c + 1];
    float4 s0 = make_float4(0.f, 0.f, 0.f, 0.f);
    float4 s1 = s0, s2 = s0, s3 = s0;
    int m = s;
    for (; m + 3 < e; m += 4) {
        int i0 = g_bucket[m], i1 = g_bucket[m + 1];
        int i2 = g_bucket[m + 2], i3 = g_bucket[m + 3];
        float4 a = ((const float4*)(features + (size_t)i0 * Dn))[d4];
        float4 b = ((const float4*)(features + (size_t)i1 * Dn))[d4];
        float4 cc = ((const float4*)(features + (size_t)i2 * Dn))[d4];
        float4 dd = ((const float4*)(features + (size_t)i3 * Dn))[d4];
        s0.x += a.x;  s0.y += a.y;  s0.z += a.z;  s0.w += a.w;
        s1.x += b.x;  s1.y += b.y;  s1.z += b.z;  s1.w += b.w;
        s2.x += cc.x; s2.y += cc.y; s2.z += cc.z; s2.w += cc.w;
        s3.x += dd.x; s3.y += dd.y; s3.z += dd.z; s3.w += dd.w;
    }
    for (; m < e; m++) {
        float4 a = ((const float4*)(features + (size_t)g_bucket[m] * Dn))[d4];
        s0.x += a.x; s0.y += a.y; s0.z += a.z; s0.w += a.w;
    }
    float4 sum;
    sum.x = (s0.x + s1.x) + (s2.x + s3.x);
    sum.y = (s0.y + s1.y) + (s2.y + s3.y);
    sum.z = (s0.z + s1.z) + (s2.z + s3.z);
    sum.w = (s0.w + s1.w) + (s2.w + s3.w);
    float inv = 1.f / fmaxf((float)(e - s), 1.f);
    sum.x *= inv; sum.y *= inv; sum.z *= inv; sum.w *= inv;
    ((float4*)(g_clu + (size_t)c * Dn))[d4] = sum;
}

// ---------------- cf build + fused row-norm ----------------
__global__ void build_cf_norm_k(const int* __restrict__ indexes,
                                const float* __restrict__ features,
                                const int* __restrict__ labels,
                                const int* __restrict__ nbr) {
    int r = blockIdx.x, t = threadIdx.x;
    int b = r >> 6, k = r & 63;
    const float* src;
    if (k == 0) src = features + (size_t)indexes[b] * Dn;
    else        src = g_clu + (size_t)labels[nbr[r]] * Dn;
    const float4* s4 = (const float4*)src;
    float4* d4 = (float4*)(g_x + (size_t)r * Dn);
    float s = 0.f;
    #pragma unroll
    for (int i = t; i < Dn / 4; i += 256) {
        float4 v = s4[i];
        d4[i] = v;
        s += v.x * v.x + v.y * v.y + v.z * v.z + v.w * v.w;
    }
    __shared__ float red[8];
    #pragma unroll
    for (int o = 16; o; o >>= 1) s += __shfl_xor_sync(0xffffffffu, s, o);
    if ((t & 31) == 0) red[t >> 5] = s;
    __syncthreads();
    if (t < 8) {
        float v = red[t];
        #pragma unroll
        for (int o = 4; o; o >>= 1) v += __shfl_xor_sync(0xffu, v, o);
        if (t == 0) g_rinv[r] = 1.f / sqrtf(v);
    }
}

// ---------------- tensor-core helpers ----------------
__device__ __forceinline__ void ldsm4(unsigned* r, unsigned a) {
    asm volatile("ldmatrix.sync.aligned.m8n8.x4.shared.b16 {%0,%1,%2,%3}, [%4];"
        : "=r"(r[0]), "=r"(r[1]), "=r"(r[2]), "=r"(r[3]) : "r"(a));
}
__device__ __forceinline__ void ldsm4t(unsigned* r, unsigned a) {
    asm volatile("ldmatrix.sync.aligned.m8n8.x4.trans.shared.b16 {%0,%1,%2,%3}, [%4];"
        : "=r"(r[0]), "=r"(r[1]), "=r"(r[2]), "=r"(r[3]) : "r"(a));
}
__device__ __forceinline__ void mma16816(float* c, const unsigned* a, unsigned b0, unsigned b1) {
    asm volatile("mma.sync.aligned.m16n8k16.row.col.f32.bf16.bf16.f32 "
        "{%0,%1,%2,%3}, {%4,%5,%6,%7}, {%8,%9}, {%0,%1,%2,%3};"
        : "+f"(c[0]), "+f"(c[1]), "+f"(c[2]), "+f"(c[3])
        : "r"(a[0]), "r"(a[1]), "r"(a[2]), "r"(a[3]), "r"(b0), "r"(b1));
}
__device__ __forceinline__ void cpasync16(unsigned dst, const void* src) {
    asm volatile("cp.async.cg.shared.global [%0], [%1], 16;"
        :: "r"(dst), "l"(__cvta_generic_to_global(src)));
}
__device__ __forceinline__ void cpcommit() {
    asm volatile("cp.async.commit_group;");
}

// ---------------- A partials = cf cf^T over K-chunk 256 (split-bf16 TC) ----------------
// grid (8, Bn), 256 threads; C = Xhi Xhi^T + Xhi Xlo^T + Xlo Xhi^T (fp32 acc)
__global__ void __launch_bounds__(256) absplit_k() {
    __shared__ __nv_bfloat16 Shi[2][64 * 64];
    __shared__ __nv_bfloat16 Slo[2][64 * 64];
    int chunk = blockIdx.x, b = blockIdx.y, tid = threadIdx.x;
    int lane = tid & 31, warp = tid >> 5;
    int wm = (warp & 3) * 16, wn = (warp >> 2) * 32;
    unsigned hi_u = (unsigned)__cvta_generic_to_shared(Shi);
    unsigned lo_u = (unsigned)__cvta_generic_to_shared(Slo);

    int lr = tid >> 2;             // 0..63 loader row
    int lc = (tid & 3) * 16;       // loader col base
    const float* src = g_x + (size_t)(b * 64 + lr) * Dn + chunk * 256 + lc;

    float f[16];
    float acc[4][4] = {};

    {
        const float4* p = (const float4*)src;
        #pragma unroll
        for (int i = 0; i < 4; i++) *(float4*)&f[i * 4] = p[i];
    }

    #pragma unroll
    for (int t = 0; t < 4; t++) {
        int s = t & 1;
        {
            __nv_bfloat16 h[16], l[16];
            #pragma unroll
            for (int i = 0; i < 16; i++) {
                h[i] = __float2bfloat16(f[i]);
                l[i] = __float2bfloat16(f[i] - __bfloat162float(h[i]));
            }
            int c0 = lc >> 3;
            #pragma unroll
            for (int half = 0; half < 2; half++) {
                int c = c0 + half;
                int off = lr * 64 + ((c ^ (lr & 7)) * 8);
                uint4 uh, ul;
                __nv_bfloat162 t2;
                t2 = __nv_bfloat162(h[half * 8 + 0], h[half * 8 + 1]); uh.x = *(unsigned*)&t2;
                t2 = __nv_bfloat162(h[half * 8 + 2], h[half * 8 + 3]); uh.y = *(unsigned*)&t2;
                t2 = __nv_bfloat162(h[half * 8 + 4], h[half * 8 + 5]); uh.z = *(unsigned*)&t2;
                t2 = __nv_bfloat162(h[half * 8 + 6], h[half * 8 + 7]); uh.w = *(unsigned*)&t2;
                t2 = __nv_bfloat162(l[half * 8 + 0], l[half * 8 + 1]); ul.x = *(unsigned*)&t2;
                t2 = __nv_bfloat162(l[half * 8 + 2], l[half * 8 + 3]); ul.y = *(unsigned*)&t2;
                t2 = __nv_bfloat162(l[half * 8 + 4], l[half * 8 + 5]); ul.z = *(unsigned*)&t2;
                t2 = __nv_bfloat162(l[half * 8 + 6], l[half * 8 + 7]); ul.w = *(unsigned*)&t2;
                *(uint4*)&Shi[s][off] = uh;
                *(uint4*)&Slo[s][off] = ul;
            }
        }
        __syncthreads();
        if (t + 1 < 4) {
            const float4* p = (const float4*)(src + (t + 1) * 64);
            #pragma unroll
            for (int i = 0; i < 4; i++) *(float4*)&f[i * 4] = p[i];
        }
        unsigned base_h = hi_u + (unsigned)(s * 8192);
        unsigned base_l = lo_u + (unsigned)(s * 8192);
        #pragma unroll
        for (int k16 = 0; k16 < 4; k16++) {
            unsigned ahi[4], alo[4], bh[2][4], bl[2][4];
            int ac = k16 * 2 + (lane >> 4);
            int arow = wm + (lane & 15);
            unsigned aoff = (unsigned)((arow * 64 + ((ac ^ (arow & 7)) * 8)) * 2);
            ldsm4(ahi, base_h + aoff);
            ldsm4(alo, base_l + aoff);
            #pragma unroll
            for (int nt = 0; nt < 2; nt++) {
                int brow = wn + nt * 16 + (lane & 15);
                unsigned boff = (unsigned)((brow * 64 + ((ac ^ (brow & 7)) * 8)) * 2);
                ldsm4(bh[nt], base_h + boff);
                ldsm4(bl[nt], base_l + boff);
            }
            #pragma unroll
            for (int nt = 0; nt < 2; nt++) {
                mma16816(acc[nt * 2 + 0], ahi, bh[nt][0], bh[nt][2]);
                mma16816(acc[nt * 2 + 0], ahi, bl[nt][0], bl[nt][2]);
                mma16816(acc[nt * 2 + 0], alo, bh[nt][0], bh[nt][2]);
                mma16816(acc[nt * 2 + 1], ahi, bh[nt][1], bh[nt][3]);
                mma16816(acc[nt * 2 + 1], ahi, bl[nt][1], bl[nt][3]);
                mma16816(acc[nt * 2 + 1], alo, bh[nt][1], bh[nt][3]);
            }
        }
        __syncthreads();
    }

    // write partials (unscaled)
    float* dst = g_apart + (size_t)(chunk * Bn + b) * 4096;
    int gid = lane >> 2, tid4 = lane & 3;
    #pragma unroll
    for (int t = 0; t < 4; t++) {
        int n = wn + t * 8 + tid4 * 2;
        int m = wm + gid;
        dst[m * 64 + n]           = acc[t][0];
        dst[m * 64 + n + 1]       = acc[t][1];
        dst[(m + 8) * 64 + n]     = acc[t][2];
        dst[(m + 8) * 64 + n + 1] = acc[t][3];
    }
}

// fused: deterministic reduce of 8 partials (+/5) -> keep + mutual top-5 -> bf16 adj
__global__ void __launch_bounds__(256) maskred_k(const int* __restrict__ labels,
                                                 const int* __restrict__ nbr) {
    __shared__ float As[64][65];
    __shared__ unsigned long long rm[64];
    __shared__ int lab[64];
    __shared__ int keep[64];
    int b = blockIdx.x, t = threadIdx.x;   // 256 threads
    for (int loc = t; loc < 4096; loc += 256) {
        float s = 0.f;
        #pragma unroll
        for (int c = 0; c < 8; c++) s += g_apart[(size_t)(c * Bn + b) * 4096 + loc];
        As[loc >> 6][loc & 63] = s * 0.2f;
    }
    if (t < 64) lab[t] = labels[nbr[b * 64 + t]];
    __syncthreads();
    if (t < 64) {
        int dup = 0;
        for (int j = 0; j < t; j++) dup |= (lab[j] == lab[t]);
        keep[t] = !dup;
        unsigned long long sel = 0ULL;
        for (int r = 0; r < 5; r++) {
            float best = -3.4e38f; int bi = 0;
            for (int j = 0; j < 64; j++) {
                float v = As[t][j];
                if (!((sel >> j) & 1ULL) && v > best) { best = v; bi = j; }
            }
            sel |= 1ULL << bi;
        }
        rm[t] = sel;
    }
    __syncthreads();
    if (t < 64) {
        bool kt = keep[t];
        for (int j = 0; j < 64; j++) {
            bool mm = kt && keep[j] && ((rm[t] >> j) & 1ULL) && ((rm[j] >> t) & 1ULL);
            g_adjb[(b * 64 + t) * 64 + j] = __float2bfloat16(mm ? As[t][j] : 0.f);
        }
    }
}

// fused center + agg: computes x = cf*rinv - q (row 0 exact 0), writes bf16 x to
// g_catb[:,0:Dn], then agg = adj @ x -> g_catb[:,Dn:2Dn]. grid (Dn/128, Bn), 256 thr.
__global__ void __launch_bounds__(256) bagg_k() {
    __shared__ __nv_bfloat16 Aj[64 * 64];
    __shared__ __nv_bfloat16 Xs[64 * 128];
    int b = blockIdx.y, d0 = blockIdx.x * 128;
    int tid = threadIdx.x, lane = tid & 31, warp = tid >> 5;
    unsigned aj_u = (unsigned)__cvta_generic_to_shared(Aj);
    unsigned xs_u = (unsigned)__cvta_generic_to_shared(Xs);

    // --- centered x: each thread handles row lr, 4 chunks (stride-4 interleave) ---
    int lr = tid >> 2;
    const float4* rsrc = (const float4*)(g_x + (size_t)(b * 64 + lr) * Dn + d0);
    const float4* qsrc = (const float4*)(g_x + (size_t)(b * 64) * Dn + d0);
    float rv = g_rinv[b * 64 + lr];
    float r0 = g_rinv[b * 64];
    #pragma unroll
    for (int i = 0; i < 4; i++) {
        int ch = (tid & 3) + i * 4;            // chunk of 8 cols
        float4 a0 = rsrc[ch * 2], a1 = rsrc[ch * 2 + 1];
        float4 q0 = qsrc[ch * 2], q1 = qsrc[ch * 2 + 1];
        __nv_bfloat162 p0 = __floats2bfloat162_rn(a0.x * rv - q0.x * r0, a0.y * rv - q0.y * r0);
        __nv_bfloat162 p1 = __floats2bfloat162_rn(a0.z * rv - q0.z * r0, a0.w * rv - q0.w * r0);
        __nv_bfloat162 p2 = __floats2bfloat162_rn(a1.x * rv - q1.x * r0, a1.y * rv - q1.y * r0);
        __nv_bfloat162 p3 = __floats2bfloat162_rn(a1.z * rv - q1.z * r0, a1.w * rv - q1.w * r0);
        uint4 u;
        u.x = *(unsigned*)&p0; u.y = *(unsigned*)&p1;
        u.z = *(unsigned*)&p2; u.w = *(unsigned*)&p3;
        int cs = (ch & 8) | ((ch & 7) ^ (lr & 7));
        *(uint4*)(Xs + lr * 128 + cs * 8) = u;
        *(uint4*)&g_catb[(size_t)(b * 64 + lr) * CDn + d0 + ch * 8] = u;
    }
    // --- adjacency load (swizzled) ---
    {
        int ar = tid >> 2, ac0 = (tid & 3) * 2;
        const __nv_bfloat16* asrc = g_adjb + (size_t)(b * 64 + ar) * 64 + ac0 * 8;
        #pragma unroll
        for (int i = 0; i < 2; i++) {
            uint4 v = *(const uint4*)(asrc + i * 8);
            int c = ac0 + i;
            *(uint4*)(Aj + ar * 64 + ((c ^ (ar & 7)) * 8)) = v;
        }
    }
    __syncthreads();

    // --- agg = adj @ x : 8 warps, each owns n16 strip ---
    int wn = warp * 16;
    float acc[4][2][4] = {};
    #pragma unroll
    for (int k16 = 0; k16 < 4; k16++) {
        unsigned afr[4][4], bfr[4];
        #pragma unroll
        for (int mi = 0; mi < 4; mi++) {
            int row = mi * 16 + (lane & 15);
            int c = k16 * 2 + (lane >> 4);
            ldsm4(afr[mi], aj_u + (row * 64 + ((c ^ (row & 7)) * 8)) * 2);
        }
        {
            int krow = k16 * 16 + (lane & 15);
            int c = (wn >> 3) + (lane >> 4);
            int cs = (c & 8) | ((c & 7) ^ (krow & 7));
            ldsm4t(bfr, xs_u + (krow * 128 + cs * 8) * 2);
        }
        #pragma unroll
        for (int mi = 0; mi < 4; mi++) {
            mma16816(acc[mi][0], afr[mi], bfr[0], bfr[1]);
            mma16816(acc[mi][1], afr[mi], bfr[2], bfr[3]);
        }
    }
    int rr = lane >> 2, cc = (lane & 3) * 2;
    #pragma unroll
    for (int mi = 0; mi < 4; mi++) {
        int gm = mi * 16 + rr;
        #pragma unroll
        for (int ni = 0; ni < 2; ni++) {
            int gn = wn + ni * 8 + cc;
            size_t base0 = (size_t)(b * 64 + gm) * CDn + Dn + d0 + gn;
            size_t base1 = (size_t)(b * 64 + gm + 8) * CDn + Dn + d0 + gn;
            *(__nv_bfloat162*)&g_catb[base0] = __floats2bfloat162_rn(acc[mi][ni][0], acc[mi][ni][1]);
            *(__nv_bfloat162*)&g_catb[base1] = __floats2bfloat162_rn(acc[mi][ni][2], acc[mi][ni][3]);
        }
    }
}

// ---------------- 4-stage pipelined bf16 tensor-core GEMMs ----------------
// BM=64, BN=128, BK=64; 256 threads = 8 warps (2M x 4N), warp tile 32x32.
// MODE 0: h  = relu(catb @ wb + conv_b)  -> g_hb  (bf16), K=4096
// MODE 1: h1 = prelu(hb @ w1b + b1, pa)  -> g_h1b (bf16), K=512
template <int MODE>
__global__ void __launch_bounds__(256) mgemm_k(const float* __restrict__ bias,
                                               const float* __restrict__ pa) {
    constexpr int Kd = (MODE == 0) ? CDn : NH;
    constexpr int nk = Kd / 64;
    const __nv_bfloat16* A = (MODE == 0) ? g_catb : g_hb;
    const __nv_bfloat16* W = (MODE == 0) ? g_wb : g_w1b;
    extern __shared__ __nv_bfloat16 smem[];
    int tid = threadIdx.x;
    int lane = tid & 31, warp = tid >> 5;
    int wm = (warp & 1) * 32, wn = (warp >> 1) * 32;
    int m0 = blockIdx.y * 64, n0 = blockIdx.x * 128;
    unsigned as_u = (unsigned)__cvta_generic_to_shared(smem);
    unsigned bs_u = as_u + 4 * 8192;

    int ar = tid >> 2, ac0 = (tid & 3) * 2;
    int br = tid >> 2, bc0 = (tid & 3) * 4;
    const __nv_bfloat16* Ag = A + (size_t)(m0 + ar) * Kd + ac0 * 8;
    const __nv_bfloat16* Wg = W + (size_t)br * NH + n0 + bc0 * 8;

    auto issue = [&](int it) {
        int s = it & 3;
        int k0 = it * 64;
        unsigned as_s = as_u + (unsigned)(s * 8192);
        unsigned bs_s = bs_u + (unsigned)(s * 16384);
        #pragma unroll
        for (int i = 0; i < 2; i++) {
            int c = ac0 + i;
            cpasync16(as_s + (unsigned)((ar * 64 + ((c ^ (ar & 7)) * 8)) * 2),
                      Ag + k0 + i * 8);
        }
        #pragma unroll
        for (int i = 0; i < 4; i++) {
            int c = bc0 + i;
            int cs = (c & 8) | ((c & 7) ^ (br & 7));
            cpasync16(bs_s + (unsigned)((br * 128 + cs * 8) * 2),
                      Wg + (size_t)k0 * NH + i * 8);
        }
        cpcommit();
    };

    float acc[2][4][4] = {};
    issue(0); issue(1); issue(2);
    for (int it = 0; it < nk; it++) {
        int s = it & 3;
        asm volatile("cp.async.wait_group 2;");
        __syncthreads();
        if (it + 3 < nk) issue(it + 3);
        unsigned as_s = as_u + (unsigned)(s * 8192);
        unsigned bs_s = bs_u + (unsigned)(s * 16384);
        #pragma unroll
        for (int k16 = 0; k16 < 4; k16++) {
            unsigned afr[2][4], bfr[2][4];
            #pragma unroll
            for (int mi = 0; mi < 2; mi++) {
                int row = wm + mi * 16 + (lane & 15);
                int c = k16 * 2 + (lane >> 4);
                ldsm4(afr[mi], as_s + (row * 64 + ((c ^ (row & 7)) * 8)) * 2);
            }
            #pragma unroll
            for (int ni = 0; ni < 2; ni++) {
                int krow = k16 * 16 + (lane & 15);
                int c = (wn >> 3) + ni * 2 + (lane >> 4);
                int cs = (c & 8) | ((c & 7) ^ (krow & 7));
                ldsm4t(bfr[ni], bs_s + (krow * 128 + cs * 8) * 2);
            }
            #pragma unroll
            for (int mi = 0; mi < 2; mi++)
                #pragma unroll
                for (int ni = 0; ni < 2; ni++) {
                    mma16816(acc[mi][ni * 2],     afr[mi], bfr[ni][0], bfr[ni][1]);
                    mma16816(acc[mi][ni * 2 + 1], afr[mi], bfr[ni][2], bfr[ni][3]);
                }
        }
    }

    int rr = lane >> 2, cc = (lane & 3) * 2;
    #pragma unroll
    for (int mi = 0; mi < 2; mi++) {
        int gm = m0 + wm + mi * 16 + rr;
        #pragma unroll
        for (int ni = 0; ni < 4; ni++) {
            int gn = n0 + wn + ni * 8 + cc;
            float b0 = bias[gn], b1 = bias[gn + 1];
            float v0 = acc[mi][ni][0] + b0;
            float v1 = acc[mi][ni][1] + b1;
            float v2 = acc[mi][ni][2] + b0;
            float v3 = acc[mi][ni][3] + b1;
            if (MODE == 0) {
                v0 = fmaxf(v0, 0.f); v1 = fmaxf(v1, 0.f);
                v2 = fmaxf(v2, 0.f); v3 = fmaxf(v3, 0.f);
                *(__nv_bfloat162*)&g_hb[(size_t)gm * NH + gn]       = __floats2bfloat162_rn(v0, v1);
                *(__nv_bfloat162*)&g_hb[(size_t)(gm + 8) * NH + gn] = __floats2bfloat162_rn(v2, v3);
            } else {
                float p0 = pa[gn], p1 = pa[gn + 1];
                v0 = (v0 > 0.f) ? v0 : p0 * v0;
                v1 = (v1 > 0.f) ? v1 : p1 * v1;
                v2 = (v2 > 0.f) ? v2 : p0 * v2;
                v3 = (v3 > 0.f) ? v3 : p1 * v3;
                *(__nv_bfloat162*)&g_h1b[(size_t)gm * NH + gn]       = __floats2bfloat162_rn(v0, v1);
                *(__nv_bfloat162*)&g_h1b[(size_t)(gm + 8) * NH + gn] = __floats2bfloat162_rn(v2, v3);
            }
        }
    }
}

// logits = h1 @ w2 + b2 ; softmax over 2 (h1 in bf16)
__global__ void fc2_softmax_k(const float* __restrict__ w2,
                              const float* __restrict__ b2,
                              float* __restrict__ out) {
    int gw = (blockIdx.x * blockDim.x + threadIdx.x) >> 5;
    int lane = threadIdx.x & 31;
    int nw = (gridDim.x * blockDim.x) >> 5;
    for (int r = gw; r < RWS; r += nw) {
        const __nv_bfloat162* h2 = (const __nv_bfloat162*)(g_h1b + (size_t)r * NH);
        float s0 = 0.f, s1 = 0.f;
        #pragma unroll
        for (int i = lane; i < NH / 2; i += 32) {
            float2 v = __bfloat1622float2(h2[i]);
            s0 += v.x * w2[4 * i]     + v.y * w2[4 * i + 2];
            s1 += v.x * w2[4 * i + 1] + v.y * w2[4 * i + 3];
        }
        #pragma unroll
        for (int o = 16; o; o >>= 1) {
            s0 += __shfl_xor_sync(0xffffffffu, s0, o);
            s1 += __shfl_xor_sync(0xffffffffu, s1, o);
        }
        if (lane == 0) {
            float l0 = s0 + b2[0], l1 = s1 + b2[1];
            float m = fmaxf(l0, l1);
            float e0 = expf(l0 - m), e1 = expf(l1 - m);
            float inv = 1.f / (e0 + e1);
            out[2 * r] = e0 * inv;
            out[2 * r + 1] = e1 * inv;
        }
    }
}

// ---------------- launch ----------------
extern "C" void kernel_launch(void* const* d_in, const int* in_sizes, int n_in,
                              void* d_out, int out_size) {
    const int*   indexes  = (const int*)d_in[0];
    const float* features = (const float*)d_in[1];
    const int*   labels   = (const int*)d_in[2];
    const int*   nbr      = (const int*)d_in[3];
    const float* conv_w   = (const float*)d_in[4];
    const float* conv_b   = (const float*)d_in[5];
    const float* w1       = (const float*)d_in[6];
    const float* b1       = (const float*)d_in[7];
    const float* pa       = (const float*)d_in[8];
    const float* w2       = (const float*)d_in[9];
    const float* b2       = (const float*)d_in[10];
    float* out = (float*)d_out;

    const int MGEMM_SMEM = 4 * (8192 + 16384);   // 96 KB dynamic (4 stages)
    cudaFuncSetAttribute(mgemm_k<0>, cudaFuncAttributeMaxDynamicSharedMemorySize, MGEMM_SMEM);
    cudaFuncSetAttribute(mgemm_k<1>, cudaFuncAttributeMaxDynamicSharedMemorySize, MGEMM_SMEM);

    bucket_k<<<1, 1024>>>(labels, nbr);                               // 0
    sortbucket_k<<<(NCn + 255) / 256, 256>>>();                       // 1
    convw_k<<<(CDn * NH + 255) / 256, 256>>>(conv_w, w1);             // 2
    clumean_k<<<dim3(Dn / 1024, NCn), 256>>>(features);               // 3 (profiled slot)
    build_cf_norm_k<<<RWS, 256>>>(indexes, features, labels, nbr);    // 4
    absplit_k<<<dim3(8, Bn), 256>>>();                                // 5
    maskred_k<<<Bn, 256>>>(labels, nbr);                              // 6
    bagg_k<<<dim3(Dn / 128, Bn), 256>>>();                            // 7 (center fused)
    mgemm_k<0><<<dim3(NH / 128, RWS / 64), 256, MGEMM_SMEM>>>(conv_b, nullptr);
    mgemm_k<1><<<dim3(NH / 128, RWS / 64), 256, MGEMM_SMEM>>>(b1, pa);
    fc2_softmax_k<<<64, 256>>>(w2, b2, out);
}

// round 14
// speedup vs baseline: 1.5768x; 1.0782x over previous
#include <cuda_runtime.h>
#include <cuda_bf16.h>
#include <stdint.h>
#include <cstdint>
#include <math.h>

// ---------------- problem constants ----------------
#define Bn   64
#define Kn   64
#define Np   32768
#define Dn   2048
#define NCn  2048
#define NH   512
#define CDn  4096      // 2*Dn
#define RWS  4096      // Bn*Kn

// ---------------- device scratch ----------------
__device__ int   g_offsets[NCn + 1];
__device__ int   g_bucket[Np];
__device__ int   g_used[NCn];
__device__ float g_clu[(size_t)NCn * Dn];          // 16 MB cluster means
__device__ float g_x[(size_t)RWS * Dn];            // 32 MB fp32 raw cf
__device__ __nv_bfloat16 g_catb[(size_t)RWS * CDn];// 32 MB bf16 [x | agg]
__device__ __nv_bfloat16 g_adjb[RWS * Kn];         // 0.5 MB bf16 masked adj
__device__ float g_apart[8 * Bn * Kn * Kn];        // 8 MB split-K partials
__device__ float g_rinv[RWS];
__device__ __nv_bfloat16 g_hb[(size_t)RWS * NH];   // 4 MB
__device__ __nv_bfloat16 g_h1b[(size_t)RWS * NH];  // 4 MB
__device__ __nv_bfloat16 g_wb[(size_t)CDn * NH];   // 4 MB
__device__ __nv_bfloat16 g_w1b[NH * NH];           // 0.5 MB

// ---------------- prep: block 0 = bucket (count+scan+scatter+used-mark),
// ----------------       blocks 1..33 = weight conversion to bf16 ----------------
__global__ void __launch_bounds__(1024) prep_k(const int* __restrict__ labels,
                                               const int* __restrict__ nbr,
                                               const float* __restrict__ w,
                                               const float* __restrict__ w1) {
    __shared__ int s[NCn];
    __shared__ int cur[NCn];
    int t = threadIdx.x;
    if (blockIdx.x != 0) {
        // weight conversion across 33 blocks x 1024 threads
        int base = (blockIdx.x - 1) * 1024 + t;
        int stride = 33 * 1024;
        for (int i = base; i < CDn * NH; i += stride) g_wb[i] = __float2bfloat16(w[i]);
        for (int i = base; i < NH * NH; i += stride)  g_w1b[i] = __float2bfloat16(w1[i]);
        return;
    }
    s[t] = 0; s[t + 1024] = 0;
    g_used[t] = 0; g_used[t + 1024] = 0;
    __syncthreads();
    for (int n = t; n < Np; n += 1024) atomicAdd(&s[labels[n]], 1);
    for (int n = t; n < Bn * Kn; n += 1024) g_used[labels[nbr[n]]] = 1;
    __syncthreads();
    for (int off = 1; off < NCn; off <<= 1) {
        int v0 = (t >= off) ? s[t - off] : 0;
        int v1 = s[t + 1024 - off];
        __syncthreads();
        s[t]        += v0;
        s[t + 1024] += v1;
        __syncthreads();
    }
    int off0 = (t == 0) ? 0 : s[t - 1];
    int off1 = s[t + 1023];
    g_offsets[t]        = off0;
    g_offsets[t + 1024] = off1;
    if (t == 0) g_offsets[NCn] = s[NCn - 1];
    cur[t] = off0; cur[t + 1024] = off1;
    __syncthreads();
    for (int n = t; n < Np; n += 1024) {
        int pos = atomicAdd(&cur[labels[n]], 1);
        g_bucket[pos] = n;
    }
}

// float4, 4 accumulator streams; local smem sort for deterministic order;
// only used clusters; grid (Dn/1024, NCn), 256 thr
__global__ void __launch_bounds__(256) clumean_k(const float* __restrict__ features) {
    int c = blockIdx.y;
    if (!g_used[c]) return;
    __shared__ int lst[512];
    int t = threadIdx.x;
    int s = g_offsets[c], e = g_offsets[c + 1];
    int n = e - s;
    bool local = (n <= 512);
    if (local) {
        for (int i = t; i < n; i += 256) lst[i] = g_bucket[s + i];
        __syncthreads();
        if (t == 0) {
            for (int i = 1; i < n; i++) {
                int v = lst[i];
                int j = i - 1;
                while (j >= 0 && lst[j] > v) { lst[j + 1] = lst[j]; j--; }
                lst[j + 1] = v;
            }
        }
        __syncthreads();
    }
    int d4 = blockIdx.x * 256 + t;                 // float4 column index
    float4 s0 = make_float4(0.f, 0.f, 0.f, 0.f);
    float4 s1 = s0, s2 = s0, s3 = s0;
    int m = 0;
    for (; m + 3 < n; m += 4) {
        int i0 = local ? lst[m]     : g_bucket[s + m];
        int i1 = local ? lst[m + 1] : g_bucket[s + m + 1];
        int i2 = local ? lst[m + 2] : g_bucket[s + m + 2];
        int i3 = local ? lst[m + 3] : g_bucket[s + m + 3];
        float4 a = ((const float4*)(features + (size_t)i0 * Dn))[d4];
        float4 b = ((const float4*)(features + (size_t)i1 * Dn))[d4];
        float4 cc = ((const float4*)(features + (size_t)i2 * Dn))[d4];
        float4 dd = ((const float4*)(features + (size_t)i3 * Dn))[d4];
        s0.x += a.x;  s0.y += a.y;  s0.z += a.z;  s0.w += a.w;
        s1.x += b.x;  s1.y += b.y;  s1.z += b.z;  s1.w += b.w;
        s2.x += cc.x; s2.y += cc.y; s2.z += cc.z; s2.w += cc.w;
        s3.x += dd.x; s3.y += dd.y; s3.z += dd.z; s3.w += dd.w;
    }
    for (; m < n; m++) {
        int i0 = local ? lst[m] : g_bucket[s + m];
        float4 a = ((const float4*)(features + (size_t)i0 * Dn))[d4];
        s0.x += a.x; s0.y += a.y; s0.z += a.z; s0.w += a.w;
    }
    float4 sum;
    sum.x = (s0.x + s1.x) + (s2.x + s3.x);
    sum.y = (s0.y + s1.y) + (s2.y + s3.y);
    sum.z = (s0.z + s1.z) + (s2.z + s3.z);
    sum.w = (s0.w + s1.w) + (s2.w + s3.w);
    float inv = 1.f / fmaxf((float)n, 1.f);
    sum.x *= inv; sum.y *= inv; sum.z *= inv; sum.w *= inv;
    ((float4*)(g_clu + (size_t)c * Dn))[d4] = sum;
}

// ---------------- cf build + fused row-norm ----------------
__global__ void build_cf_norm_k(const int* __restrict__ indexes,
                                const float* __restrict__ features,
                                const int* __restrict__ labels,
                                const int* __restrict__ nbr) {
    int r = blockIdx.x, t = threadIdx.x;
    int b = r >> 6, k = r & 63;
    const float* src;
    if (k == 0) src = features + (size_t)indexes[b] * Dn;
    else        src = g_clu + (size_t)labels[nbr[r]] * Dn;
    const float4* s4 = (const float4*)src;
    float4* d4 = (float4*)(g_x + (size_t)r * Dn);
    float s = 0.f;
    #pragma unroll
    for (int i = t; i < Dn / 4; i += 256) {
        float4 v = s4[i];
        d4[i] = v;
        s += v.x * v.x + v.y * v.y + v.z * v.z + v.w * v.w;
    }
    __shared__ float red[8];
    #pragma unroll
    for (int o = 16; o; o >>= 1) s += __shfl_xor_sync(0xffffffffu, s, o);
    if ((t & 31) == 0) red[t >> 5] = s;
    __syncthreads();
    if (t < 8) {
        float v = red[t];
        #pragma unroll
        for (int o = 4; o; o >>= 1) v += __shfl_xor_sync(0xffu, v, o);
        if (t == 0) g_rinv[r] = 1.f / sqrtf(v);
    }
}

// ---------------- tensor-core helpers ----------------
__device__ __forceinline__ void ldsm4(unsigned* r, unsigned a) {
    asm volatile("ldmatrix.sync.aligned.m8n8.x4.shared.b16 {%0,%1,%2,%3}, [%4];"
        : "=r"(r[0]), "=r"(r[1]), "=r"(r[2]), "=r"(r[3]) : "r"(a));
}
__device__ __forceinline__ void ldsm4t(unsigned* r, unsigned a) {
    asm volatile("ldmatrix.sync.aligned.m8n8.x4.trans.shared.b16 {%0,%1,%2,%3}, [%4];"
        : "=r"(r[0]), "=r"(r[1]), "=r"(r[2]), "=r"(r[3]) : "r"(a));
}
__device__ __forceinline__ void mma16816(float* c, const unsigned* a, unsigned b0, unsigned b1) {
    asm volatile("mma.sync.aligned.m16n8k16.row.col.f32.bf16.bf16.f32 "
        "{%0,%1,%2,%3}, {%4,%5,%6,%7}, {%8,%9}, {%0,%1,%2,%3};"
        : "+f"(c[0]), "+f"(c[1]), "+f"(c[2]), "+f"(c[3])
        : "r"(a[0]), "r"(a[1]), "r"(a[2]), "r"(a[3]), "r"(b0), "r"(b1));
}
__device__ __forceinline__ void cpasync16(unsigned dst, const void* src) {
    asm volatile("cp.async.cg.shared.global [%0], [%1], 16;"
        :: "r"(dst), "l"(__cvta_generic_to_global(src)));
}
__device__ __forceinline__ void cpcommit() {
    asm volatile("cp.async.commit_group;");
}

// ---------------- A partials = cf cf^T over K-chunk 256 (split-bf16 TC) ----------------
// grid (8, Bn), 256 threads; C = Xhi Xhi^T + Xhi Xlo^T + Xlo Xhi^T (fp32 acc)
__global__ void __launch_bounds__(256) absplit_k() {
    __shared__ __nv_bfloat16 Shi[2][64 * 64];
    __shared__ __nv_bfloat16 Slo[2][64 * 64];
    int chunk = blockIdx.x, b = blockIdx.y, tid = threadIdx.x;
    int lane = tid & 31, warp = tid >> 5;
    int wm = (warp & 3) * 16, wn = (warp >> 2) * 32;
    unsigned hi_u = (unsigned)__cvta_generic_to_shared(Shi);
    unsigned lo_u = (unsigned)__cvta_generic_to_shared(Slo);

    int lr = tid >> 2;             // 0..63 loader row
    int lc = (tid & 3) * 16;       // loader col base
    const float* src = g_x + (size_t)(b * 64 + lr) * Dn + chunk * 256 + lc;

    float f[16];
    float acc[4][4] = {};

    {
        const float4* p = (const float4*)src;
        #pragma unroll
        for (int i = 0; i < 4; i++) *(float4*)&f[i * 4] = p[i];
    }

    #pragma unroll
    for (int t = 0; t < 4; t++) {
        int s = t & 1;
        {
            __nv_bfloat16 h[16], l[16];
            #pragma unroll
            for (int i = 0; i < 16; i++) {
                h[i] = __float2bfloat16(f[i]);
                l[i] = __float2bfloat16(f[i] - __bfloat162float(h[i]));
            }
            int c0 = lc >> 3;
            #pragma unroll
            for (int half = 0; half < 2; half++) {
                int c = c0 + half;
                int off = lr * 64 + ((c ^ (lr & 7)) * 8);
                uint4 uh, ul;
                __nv_bfloat162 t2;
                t2 = __nv_bfloat162(h[half * 8 + 0], h[half * 8 + 1]); uh.x = *(unsigned*)&t2;
                t2 = __nv_bfloat162(h[half * 8 + 2], h[half * 8 + 3]); uh.y = *(unsigned*)&t2;
                t2 = __nv_bfloat162(h[half * 8 + 4], h[half * 8 + 5]); uh.z = *(unsigned*)&t2;
                t2 = __nv_bfloat162(h[half * 8 + 6], h[half * 8 + 7]); uh.w = *(unsigned*)&t2;
                t2 = __nv_bfloat162(l[half * 8 + 0], l[half * 8 + 1]); ul.x = *(unsigned*)&t2;
                t2 = __nv_bfloat162(l[half * 8 + 2], l[half * 8 + 3]); ul.y = *(unsigned*)&t2;
                t2 = __nv_bfloat162(l[half * 8 + 4], l[half * 8 + 5]); ul.z = *(unsigned*)&t2;
                t2 = __nv_bfloat162(l[half * 8 + 6], l[half * 8 + 7]); ul.w = *(unsigned*)&t2;
                *(uint4*)&Shi[s][off] = uh;
                *(uint4*)&Slo[s][off] = ul;
            }
        }
        __syncthreads();
        if (t + 1 < 4) {
            const float4* p = (const float4*)(src + (t + 1) * 64);
            #pragma unroll
            for (int i = 0; i < 4; i++) *(float4*)&f[i * 4] = p[i];
        }
        unsigned base_h = hi_u + (unsigned)(s * 8192);
        unsigned base_l = lo_u + (unsigned)(s * 8192);
        #pragma unroll
        for (int k16 = 0; k16 < 4; k16++) {
            unsigned ahi[4], alo[4], bh[2][4], bl[2][4];
            int ac = k16 * 2 + (lane >> 4);
            int arow = wm + (lane & 15);
            unsigned aoff = (unsigned)((arow * 64 + ((ac ^ (arow & 7)) * 8)) * 2);
            ldsm4(ahi, base_h + aoff);
            ldsm4(alo, base_l + aoff);
            #pragma unroll
            for (int nt = 0; nt < 2; nt++) {
                int brow = wn + nt * 16 + (lane & 15);
                unsigned boff = (unsigned)((brow * 64 + ((ac ^ (brow & 7)) * 8)) * 2);
                ldsm4(bh[nt], base_h + boff);
                ldsm4(bl[nt], base_l + boff);
            }
            #pragma unroll
            for (int nt = 0; nt < 2; nt++) {
                mma16816(acc[nt * 2 + 0], ahi, bh[nt][0], bh[nt][2]);
                mma16816(acc[nt * 2 + 0], ahi, bl[nt][0], bl[nt][2]);
                mma16816(acc[nt * 2 + 0], alo, bh[nt][0], bh[nt][2]);
                mma16816(acc[nt * 2 + 1], ahi, bh[nt][1], bh[nt][3]);
                mma16816(acc[nt * 2 + 1], ahi, bl[nt][1], bl[nt][3]);
                mma16816(acc[nt * 2 + 1], alo, bh[nt][1], bh[nt][3]);
            }
        }
        __syncthreads();
    }

    // write partials (unscaled)
    float* dst = g_apart + (size_t)(chunk * Bn + b) * 4096;
    int gid = lane >> 2, tid4 = lane & 3;
    #pragma unroll
    for (int t = 0; t < 4; t++) {
        int n = wn + t * 8 + tid4 * 2;
        int m = wm + gid;
        dst[m * 64 + n]           = acc[t][0];
        dst[m * 64 + n + 1]       = acc[t][1];
        dst[(m + 8) * 64 + n]     = acc[t][2];
        dst[(m + 8) * 64 + n + 1] = acc[t][3];
    }
}

// fused: deterministic reduce of 8 partials (+/5) -> keep + mutual top-5 -> bf16 adj
__global__ void __launch_bounds__(256) maskred_k(const int* __restrict__ labels,
                                                 const int* __restrict__ nbr) {
    __shared__ float As[64][65];
    __shared__ unsigned long long rm[64];
    __shared__ int lab[64];
    __shared__ int keep[64];
    int b = blockIdx.x, t = threadIdx.x;   // 256 threads
    for (int loc = t; loc < 4096; loc += 256) {
        float s = 0.f;
        #pragma unroll
        for (int c = 0; c < 8; c++) s += g_apart[(size_t)(c * Bn + b) * 4096 + loc];
        As[loc >> 6][loc & 63] = s * 0.2f;
    }
    if (t < 64) lab[t] = labels[nbr[b * 64 + t]];
    __syncthreads();
    if (t < 64) {
        int dup = 0;
        for (int j = 0; j < t; j++) dup |= (lab[j] == lab[t]);
        keep[t] = !dup;
        unsigned long long sel = 0ULL;
        for (int r = 0; r < 5; r++) {
            float best = -3.4e38f; int bi = 0;
            for (int j = 0; j < 64; j++) {
                float v = As[t][j];
                if (!((sel >> j) & 1ULL) && v > best) { best = v; bi = j; }
            }
            sel |= 1ULL << bi;
        }
        rm[t] = sel;
    }
    __syncthreads();
    if (t < 64) {
        bool kt = keep[t];
        for (int j = 0; j < 64; j++) {
            bool mm = kt && keep[j] && ((rm[t] >> j) & 1ULL) && ((rm[j] >> t) & 1ULL);
            g_adjb[(b * 64 + t) * 64 + j] = __float2bfloat16(mm ? As[t][j] : 0.f);
        }
    }
}

// fused center + agg: x = cf*rinv - q (row 0 exact 0) -> bf16 g_catb[:,0:Dn],
// then agg = adj @ x -> g_catb[:,Dn:2Dn]. grid (Dn/128, Bn), 256 thr.
__global__ void __launch_bounds__(256) bagg_k() {
    __shared__ __nv_bfloat16 Aj[64 * 64];
    __shared__ __nv_bfloat16 Xs[64 * 128];
    int b = blockIdx.y, d0 = blockIdx.x * 128;
    int tid = threadIdx.x, lane = tid & 31, warp = tid >> 5;
    unsigned aj_u = (unsigned)__cvta_generic_to_shared(Aj);
    unsigned xs_u = (unsigned)__cvta_generic_to_shared(Xs);

    int lr = tid >> 2;
    const float4* rsrc = (const float4*)(g_x + (size_t)(b * 64 + lr) * Dn + d0);
    const float4* qsrc = (const float4*)(g_x + (size_t)(b * 64) * Dn + d0);
    float rv = g_rinv[b * 64 + lr];
    float r0 = g_rinv[b * 64];
    #pragma unroll
    for (int i = 0; i < 4; i++) {
        int ch = (tid & 3) + i * 4;            // chunk of 8 cols
        float4 a0 = rsrc[ch * 2], a1 = rsrc[ch * 2 + 1];
        float4 q0 = qsrc[ch * 2], q1 = qsrc[ch * 2 + 1];
        __nv_bfloat162 p0 = __floats2bfloat162_rn(a0.x * rv - q0.x * r0, a0.y * rv - q0.y * r0);
        __nv_bfloat162 p1 = __floats2bfloat162_rn(a0.z * rv - q0.z * r0, a0.w * rv - q0.w * r0);
        __nv_bfloat162 p2 = __floats2bfloat162_rn(a1.x * rv - q1.x * r0, a1.y * rv - q1.y * r0);
        __nv_bfloat162 p3 = __floats2bfloat162_rn(a1.z * rv - q1.z * r0, a1.w * rv - q1.w * r0);
        uint4 u;
        u.x = *(unsigned*)&p0; u.y = *(unsigned*)&p1;
        u.z = *(unsigned*)&p2; u.w = *(unsigned*)&p3;
        int cs = (ch & 8) | ((ch & 7) ^ (lr & 7));
        *(uint4*)(Xs + lr * 128 + cs * 8) = u;
        *(uint4*)&g_catb[(size_t)(b * 64 + lr) * CDn + d0 + ch * 8] = u;
    }
    {
        int ar = tid >> 2, ac0 = (tid & 3) * 2;
        const __nv_bfloat16* asrc = g_adjb + (size_t)(b * 64 + ar) * 64 + ac0 * 8;
        #pragma unroll
        for (int i = 0; i < 2; i++) {
            uint4 v = *(const uint4*)(asrc + i * 8);
            int c = ac0 + i;
            *(uint4*)(Aj + ar * 64 + ((c ^ (ar & 7)) * 8)) = v;
        }
    }
    __syncthreads();

    int wn = warp * 16;
    float acc[4][2][4] = {};
    #pragma unroll
    for (int k16 = 0; k16 < 4; k16++) {
        unsigned afr[4][4], bfr[4];
        #pragma unroll
        for (int mi = 0; mi < 4; mi++) {
            int row = mi * 16 + (lane & 15);
            int c = k16 * 2 + (lane >> 4);
            ldsm4(afr[mi], aj_u + (row * 64 + ((c ^ (row & 7)) * 8)) * 2);
        }
        {
            int krow = k16 * 16 + (lane & 15);
            int c = (wn >> 3) + (lane >> 4);
            int cs = (c & 8) | ((c & 7) ^ (krow & 7));
            ldsm4t(bfr, xs_u + (krow * 128 + cs * 8) * 2);
        }
        #pragma unroll
        for (int mi = 0; mi < 4; mi++) {
            mma16816(acc[mi][0], afr[mi], bfr[0], bfr[1]);
            mma16816(acc[mi][1], afr[mi], bfr[2], bfr[3]);
        }
    }
    int rr = lane >> 2, cc = (lane & 3) * 2;
    #pragma unroll
    for (int mi = 0; mi < 4; mi++) {
        int gm = mi * 16 + rr;
        #pragma unroll
        for (int ni = 0; ni < 2; ni++) {
            int gn = wn + ni * 8 + cc;
            size_t base0 = (size_t)(b * 64 + gm) * CDn + Dn + d0 + gn;
            size_t base1 = (size_t)(b * 64 + gm + 8) * CDn + Dn + d0 + gn;
            *(__nv_bfloat162*)&g_catb[base0] = __floats2bfloat162_rn(acc[mi][ni][0], acc[mi][ni][1]);
            *(__nv_bfloat162*)&g_catb[base1] = __floats2bfloat162_rn(acc[mi][ni][2], acc[mi][ni][3]);
        }
    }
}

// ---------------- 4-stage pipelined bf16 tensor-core GEMMs ----------------
// BM=64, BN=128, BK=64; 256 threads = 8 warps (2M x 4N), warp tile 32x32.
// MODE 0: h  = relu(catb @ wb + conv_b)  -> g_hb  (bf16), K=4096
// MODE 1: h1 = prelu(hb @ w1b + b1, pa)  -> g_h1b (bf16), K=512
template <int MODE>
__global__ void __launch_bounds__(256) mgemm_k(const float* __restrict__ bias,
                                               const float* __restrict__ pa) {
    constexpr int Kd = (MODE == 0) ? CDn : NH;
    constexpr int nk = Kd / 64;
    const __nv_bfloat16* A = (MODE == 0) ? g_catb : g_hb;
    const __nv_bfloat16* W = (MODE == 0) ? g_wb : g_w1b;
    extern __shared__ __nv_bfloat16 smem[];
    int tid = threadIdx.x;
    int lane = tid & 31, warp = tid >> 5;
    int wm = (warp & 1) * 32, wn = (warp >> 1) * 32;
    int m0 = blockIdx.y * 64, n0 = blockIdx.x * 128;
    unsigned as_u = (unsigned)__cvta_generic_to_shared(smem);
    unsigned bs_u = as_u + 4 * 8192;

    int ar = tid >> 2, ac0 = (tid & 3) * 2;
    int br = tid >> 2, bc0 = (tid & 3) * 4;
    const __nv_bfloat16* Ag = A + (size_t)(m0 + ar) * Kd + ac0 * 8;
    const __nv_bfloat16* Wg = W + (size_t)br * NH + n0 + bc0 * 8;

    auto issue = [&](int it) {
        int s = it & 3;
        int k0 = it * 64;
        unsigned as_s = as_u + (unsigned)(s * 8192);
        unsigned bs_s = bs_u + (unsigned)(s * 16384);
        #pragma unroll
        for (int i = 0; i < 2; i++) {
            int c = ac0 + i;
            cpasync16(as_s + (unsigned)((ar * 64 + ((c ^ (ar & 7)) * 8)) * 2),
                      Ag + k0 + i * 8);
        }
        #pragma unroll
        for (int i = 0; i < 4; i++) {
            int c = bc0 + i;
            int cs = (c & 8) | ((c & 7) ^ (br & 7));
            cpasync16(bs_s + (unsigned)((br * 128 + cs * 8) * 2),
                      Wg + (size_t)k0 * NH + i * 8);
        }
        cpcommit();
    };

    float acc[2][4][4] = {};
    issue(0); issue(1); issue(2);
    for (int it = 0; it < nk; it++) {
        int s = it & 3;
        asm volatile("cp.async.wait_group 2;");
        __syncthreads();
        if (it + 3 < nk) issue(it + 3);
        unsigned as_s = as_u + (unsigned)(s * 8192);
        unsigned bs_s = bs_u + (unsigned)(s * 16384);
        #pragma unroll
        for (int k16 = 0; k16 < 4; k16++) {
            unsigned afr[2][4], bfr[2][4];
            #pragma unroll
            for (int mi = 0; mi < 2; mi++) {
                int row = wm + mi * 16 + (lane & 15);
                int c = k16 * 2 + (lane >> 4);
                ldsm4(afr[mi], as_s + (row * 64 + ((c ^ (row & 7)) * 8)) * 2);
            }
            #pragma unroll
            for (int ni = 0; ni < 2; ni++) {
                int krow = k16 * 16 + (lane & 15);
                int c = (wn >> 3) + ni * 2 + (lane >> 4);
                int cs = (c & 8) | ((c & 7) ^ (krow & 7));
                ldsm4t(bfr[ni], bs_s + (krow * 128 + cs * 8) * 2);
            }
            #pragma unroll
            for (int mi = 0; mi < 2; mi++)
                #pragma unroll
                for (int ni = 0; ni < 2; ni++) {
                    mma16816(acc[mi][ni * 2],     afr[mi], bfr[ni][0], bfr[ni][1]);
                    mma16816(acc[mi][ni * 2 + 1], afr[mi], bfr[ni][2], bfr[ni][3]);
                }
        }
    }

    int rr = lane >> 2, cc = (lane & 3) * 2;
    #pragma unroll
    for (int mi = 0; mi < 2; mi++) {
        int gm = m0 + wm + mi * 16 + rr;
        #pragma unroll
        for (int ni = 0; ni < 4; ni++) {
            int gn = n0 + wn + ni * 8 + cc;
            float b0 = bias[gn], b1 = bias[gn + 1];
            float v0 = acc[mi][ni][0] + b0;
            float v1 = acc[mi][ni][1] + b1;
            float v2 = acc[mi][ni][2] + b0;
            float v3 = acc[mi][ni][3] + b1;
            if (MODE == 0) {
                v0 = fmaxf(v0, 0.f); v1 = fmaxf(v1, 0.f);
                v2 = fmaxf(v2, 0.f); v3 = fmaxf(v3, 0.f);
                *(__nv_bfloat162*)&g_hb[(size_t)gm * NH + gn]       = __floats2bfloat162_rn(v0, v1);
                *(__nv_bfloat162*)&g_hb[(size_t)(gm + 8) * NH + gn] = __floats2bfloat162_rn(v2, v3);
            } else {
                float p0 = pa[gn], p1 = pa[gn + 1];
                v0 = (v0 > 0.f) ? v0 : p0 * v0;
                v1 = (v1 > 0.f) ? v1 : p1 * v1;
                v2 = (v2 > 0.f) ? v2 : p0 * v2;
                v3 = (v3 > 0.f) ? v3 : p1 * v3;
                *(__nv_bfloat162*)&g_h1b[(size_t)gm * NH + gn]       = __floats2bfloat162_rn(v0, v1);
                *(__nv_bfloat162*)&g_h1b[(size_t)(gm + 8) * NH + gn] = __floats2bfloat162_rn(v2, v3);
            }
        }
    }
}

// logits = h1 @ w2 + b2 ; softmax over 2 (h1 in bf16)
__global__ void fc2_softmax_k(const float* __restrict__ w2,
                              const float* __restrict__ b2,
                              float* __restrict__ out) {
    int gw = (blockIdx.x * blockDim.x + threadIdx.x) >> 5;
    int lane = threadIdx.x & 31;
    int nw = (gridDim.x * blockDim.x) >> 5;
    for (int r = gw; r < RWS; r += nw) {
        const __nv_bfloat162* h2 = (const __nv_bfloat162*)(g_h1b + (size_t)r * NH);
        float s0 = 0.f, s1 = 0.f;
        #pragma unroll
        for (int i = lane; i < NH / 2; i += 32) {
            float2 v = __bfloat1622float2(h2[i]);
            s0 += v.x * w2[4 * i]     + v.y * w2[4 * i + 2];
            s1 += v.x * w2[4 * i + 1] + v.y * w2[4 * i + 3];
        }
        #pragma unroll
        for (int o = 16; o; o >>= 1) {
            s0 += __shfl_xor_sync(0xffffffffu, s0, o);
            s1 += __shfl_xor_sync(0xffffffffu, s1, o);
        }
        if (lane == 0) {
            float l0 = s0 + b2[0], l1 = s1 + b2[1];
            float m = fmaxf(l0, l1);
            float e0 = expf(l0 - m), e1 = expf(l1 - m);
            float inv = 1.f / (e0 + e1);
            out[2 * r] = e0 * inv;
            out[2 * r + 1] = e1 * inv;
        }
    }
}

// ---------------- launch ----------------
extern "C" void kernel_launch(void* const* d_in, const int* in_sizes, int n_in,
                              void* d_out, int out_size) {
    const int*   indexes  = (const int*)d_in[0];
    const float* features = (const float*)d_in[1];
    const int*   labels   = (const int*)d_in[2];
    const int*   nbr      = (const int*)d_in[3];
    const float* conv_w   = (const float*)d_in[4];
    const float* conv_b   = (const float*)d_in[5];
    const float* w1       = (const float*)d_in[6];
    const float* b1       = (const float*)d_in[7];
    const float* pa       = (const float*)d_in[8];
    const float* w2       = (const float*)d_in[9];
    const float* b2       = (const float*)d_in[10];
    float* out = (float*)d_out;

    const int MGEMM_SMEM = 4 * (8192 + 16384);   // 96 KB dynamic (4 stages)
    cudaFuncSetAttribute(mgemm_k<0>, cudaFuncAttributeMaxDynamicSharedMemorySize, MGEMM_SMEM);
    cudaFuncSetAttribute(mgemm_k<1>, cudaFuncAttributeMaxDynamicSharedMemorySize, MGEMM_SMEM);

    prep_k<<<34, 1024>>>(labels, nbr, conv_w, w1);                    // 0 (bucket + convw)
    clumean_k<<<dim3(Dn / 1024, NCn), 256>>>(features);               // 1 (local sort)
    build_cf_norm_k<<<RWS, 256>>>(indexes, features, labels, nbr);    // 2
    absplit_k<<<dim3(8, Bn), 256>>>();                                // 3 (profiled slot)
    maskred_k<<<Bn, 256>>>(labels, nbr);                              // 4
    bagg_k<<<dim3(Dn / 128, Bn), 256>>>();                            // 5
    mgemm_k<0><<<dim3(NH / 128, RWS / 64), 256, MGEMM_SMEM>>>(conv_b, nullptr);
    mgemm_k<1><<<dim3(NH / 128, RWS / 64), 256, MGEMM_SMEM>>>(b1, pa);
    fc2_softmax_k<<<128, 256>>>(w2, b2, out);
}